// round 3
// baseline (speedup 1.0000x reference)
#include <cuda_runtime.h>
#include <math.h>

// ---------------------------------------------------------------------------
// Decoder layer, fp32 (round 3: all scratch buffers accessed ONLY as device
// symbols inside kernels — never passed as kernel args from host, which gave
// host-shadow addresses silently usable via ATS on GB300 = two disjoint
// copies of every buffer).
// ---------------------------------------------------------------------------

#define S 1024
#define H 2048
#define NH 32
#define NKV 8
#define D 64
#define G 4
#define E 8
#define TOPK 2
#define F 4096
#define EPS 1e-5f
#define MULT 0.125f
#define CAP 30.0f

// ------------------------------ scratch (device globals) --------------------
__device__ float g_xnorm[S * H];
__device__ float g_q[S * NH * D];
__device__ float g_k[S * NKV * D];
__device__ float g_v[S * NKV * D];
__device__ float g_attn[S * H];
__device__ float g_attnproj[S * H];
__device__ float g_hidden[S * H];
__device__ float g_h1[S * TOPK * F];
__device__ float g_hv[S * TOPK * F];
__device__ float g_gout[S * TOPK * H];
__device__ int   g_topi[S * TOPK];
__device__ float g_topw[S * TOPK];
__device__ int   g_offs[E + 1];
__device__ int   g_perm_token[S * TOPK];
__device__ int   g_tok2row[S * TOPK];

// Buffer selector — device-side only, so kernels get true device addresses.
#define BUF_XNORM 0
#define BUF_Q 1
#define BUF_K 2
#define BUF_V 3
#define BUF_ATTN 4
#define BUF_ATTNPROJ 5
#define BUF_HIDDEN 6
#define BUF_H1 7
#define BUF_HV 8
#define BUF_GOUT 9
__device__ __forceinline__ float* gbuf(int id) {
    switch (id) {
        case BUF_XNORM: return g_xnorm;
        case BUF_Q: return g_q;
        case BUF_K: return g_k;
        case BUF_V: return g_v;
        case BUF_ATTN: return g_attn;
        case BUF_ATTNPROJ: return g_attnproj;
        case BUF_HIDDEN: return g_hidden;
        case BUF_H1: return g_h1;
        case BUF_HV: return g_hv;
        default: return g_gout;
    }
}

// ------------------------------ rmsnorm ------------------------------------
// y[yid] = w * rmsnorm(x);  x = (xid < 0 ? xext : gbuf(xid))
__global__ void rmsnorm_kernel(const float* __restrict__ xext, int xid,
                               const float* __restrict__ w, int yid) {
    const float* x = (xid < 0) ? xext : gbuf(xid);
    float* y = gbuf(yid);
    int row = blockIdx.x;
    int tid = threadIdx.x;
    const float* xr = x + (size_t)row * H;
    float ss = 0.f;
    float loc[8];
#pragma unroll
    for (int t = 0; t < 8; ++t) {
        float v = xr[tid + t * 256];
        loc[t] = v;
        ss += v * v;
    }
    __shared__ float red[256];
    red[tid] = ss;
    __syncthreads();
    for (int s2 = 128; s2 > 0; s2 >>= 1) {
        if (tid < s2) red[tid] += red[tid + s2];
        __syncthreads();
    }
    float inv = rsqrtf(red[0] / (float)H + EPS);
#pragma unroll
    for (int t = 0; t < 8; ++t) {
        int c = tid + t * 256;
        y[(size_t)row * H + c] = w[c] * loc[t] * inv;
    }
}

// hidden = residual(harness ptr) + rmsnorm(gbuf(xid), w) -> gbuf(yid)
__global__ void add_rmsnorm_kernel(const float* __restrict__ residual, int xid,
                                   const float* __restrict__ w, int yid) {
    const float* x = gbuf(xid);
    float* y = gbuf(yid);
    int row = blockIdx.x;
    int tid = threadIdx.x;
    const float* xr = x + (size_t)row * H;
    float ss = 0.f;
    float loc[8];
#pragma unroll
    for (int t = 0; t < 8; ++t) {
        float v = xr[tid + t * 256];
        loc[t] = v;
        ss += v * v;
    }
    __shared__ float red[256];
    red[tid] = ss;
    __syncthreads();
    for (int s2 = 128; s2 > 0; s2 >>= 1) {
        if (tid < s2) red[tid] += red[tid + s2];
        __syncthreads();
    }
    float inv = rsqrtf(red[0] / (float)H + EPS);
#pragma unroll
    for (int t = 0; t < 8; ++t) {
        int c = tid + t * 256;
        y[(size_t)row * H + c] = residual[(size_t)row * H + c] + w[c] * loc[t] * inv;
    }
}

// out = g_hidden + rmsnorm(w0*g_gout[r0] + w1*g_gout[r1], n4)
__global__ void final_kernel(const float* __restrict__ n4,
                             float* __restrict__ out) {
    int t = blockIdx.x;
    int tid = threadIdx.x;
    int r0 = g_tok2row[2 * t], r1 = g_tok2row[2 * t + 1];
    float w0 = g_topw[2 * t], w1 = g_topw[2 * t + 1];
    const float* a = g_gout + (size_t)r0 * H;
    const float* b = g_gout + (size_t)r1 * H;
    float ss = 0.f;
    float loc[8];
#pragma unroll
    for (int k = 0; k < 8; ++k) {
        int c = tid + k * 256;
        float v = w0 * a[c] + w1 * b[c];
        loc[k] = v;
        ss += v * v;
    }
    __shared__ float red[256];
    red[tid] = ss;
    __syncthreads();
    for (int s2 = 128; s2 > 0; s2 >>= 1) {
        if (tid < s2) red[tid] += red[tid + s2];
        __syncthreads();
    }
    float inv = rsqrtf(red[0] / (float)H + EPS);
#pragma unroll
    for (int k = 0; k < 8; ++k) {
        int c = tid + k * 256;
        out[(size_t)t * H + c] = g_hidden[(size_t)t * H + c] + n4[c] * loc[k] * inv;
    }
}

// ------------------------------ SGEMM (128x128x16, 8x8/thread) -------------
// C = gbuf(cid); A = gbuf(aid); B = harness weight pointer (true device ptr).
__global__ void sgemm_kernel(int aid, const float* __restrict__ B, int cid,
                             int M, int N, int K) {
    const float* A = gbuf(aid);
    float* C = gbuf(cid);
    __shared__ float As[16 * 133];
    __shared__ float Bs[16 * 128];
    int tid = threadIdx.x;
    int tx = tid & 15, ty = tid >> 4;
    int mBase = blockIdx.y * 128;
    int nBase = blockIdx.x * 128;
    float acc[8][8];
#pragma unroll
    for (int i = 0; i < 8; ++i)
#pragma unroll
        for (int j = 0; j < 8; ++j) acc[i][j] = 0.f;

    for (int k0 = 0; k0 < K; k0 += 16) {
#pragma unroll
        for (int t = 0; t < 8; ++t) {
            int e2 = tid + t * 256;
            int r = e2 >> 4, c = e2 & 15;
            int grow = mBase + r;
            float v = 0.f;
            if (grow < M) v = A[(size_t)grow * K + k0 + c];
            As[c * 133 + r] = v;
        }
#pragma unroll
        for (int t = 0; t < 8; ++t) {
            int e2 = tid + t * 256;
            int r = e2 >> 7, c = e2 & 127;
            Bs[r * 128 + c] = B[(size_t)(k0 + r) * N + nBase + c];
        }
        __syncthreads();
#pragma unroll
        for (int kk = 0; kk < 16; ++kk) {
            float a[8], b[8];
#pragma unroll
            for (int i = 0; i < 8; ++i) a[i] = As[kk * 133 + ty + 16 * i];
#pragma unroll
            for (int j = 0; j < 8; ++j) b[j] = Bs[kk * 128 + tx + 16 * j];
#pragma unroll
            for (int i = 0; i < 8; ++i)
#pragma unroll
                for (int j = 0; j < 8; ++j) acc[i][j] += a[i] * b[j];
        }
        __syncthreads();
    }
#pragma unroll
    for (int i = 0; i < 8; ++i) {
        int row = mBase + ty + 16 * i;
        if (row < M) {
#pragma unroll
            for (int j = 0; j < 8; ++j)
                C[(size_t)row * N + nBase + tx + 16 * j] = acc[i][j];
        }
    }
}

// Grouped (per-expert) GEMM over grouped rows [g_offs[e], g_offs[e+1]).
// A row for grouped row g = use_gather ? g_perm_token[g] : g.
__global__ void sgemm_group_kernel(int aid, const float* __restrict__ Bfull,
                                   int cid, int N, int K, size_t Bstride,
                                   int use_gather) {
    const float* A = gbuf(aid);
    float* C = gbuf(cid);
    int e = blockIdx.z;
    int rbeg = g_offs[e], rend = g_offs[e + 1];
    int mBase = rbeg + blockIdx.y * 128;
    if (mBase >= rend) return;
    const float* B = Bfull + (size_t)e * Bstride;

    __shared__ float As[16 * 133];
    __shared__ float Bs[16 * 128];
    int tid = threadIdx.x;
    int tx = tid & 15, ty = tid >> 4;
    int nBase = blockIdx.x * 128;
    float acc[8][8];
#pragma unroll
    for (int i = 0; i < 8; ++i)
#pragma unroll
        for (int j = 0; j < 8; ++j) acc[i][j] = 0.f;

    for (int k0 = 0; k0 < K; k0 += 16) {
#pragma unroll
        for (int t = 0; t < 8; ++t) {
            int e2 = tid + t * 256;
            int r = e2 >> 4, c = e2 & 15;
            int grow = mBase + r;
            float v = 0.f;
            if (grow < rend) {
                int arow = use_gather ? g_perm_token[grow] : grow;
                v = A[(size_t)arow * K + k0 + c];
            }
            As[c * 133 + r] = v;
        }
#pragma unroll
        for (int t = 0; t < 8; ++t) {
            int e2 = tid + t * 256;
            int r = e2 >> 7, c = e2 & 127;
            Bs[r * 128 + c] = B[(size_t)(k0 + r) * N + nBase + c];
        }
        __syncthreads();
#pragma unroll
        for (int kk = 0; kk < 16; ++kk) {
            float a[8], b[8];
#pragma unroll
            for (int i = 0; i < 8; ++i) a[i] = As[kk * 133 + ty + 16 * i];
#pragma unroll
            for (int j = 0; j < 8; ++j) b[j] = Bs[kk * 128 + tx + 16 * j];
#pragma unroll
            for (int i = 0; i < 8; ++i)
#pragma unroll
                for (int j = 0; j < 8; ++j) acc[i][j] += a[i] * b[j];
        }
        __syncthreads();
    }
#pragma unroll
    for (int i = 0; i < 8; ++i) {
        int row = mBase + ty + 16 * i;
        if (row < rend) {
#pragma unroll
            for (int j = 0; j < 8; ++j)
                C[(size_t)row * N + nBase + tx + 16 * j] = acc[i][j];
        }
    }
}

// ------------------------------ RoPE ---------------------------------------
__global__ void rope_kernel(int xid, int nheads) {
    float* x = gbuf(xid);
    int idx = blockIdx.x * blockDim.x + threadIdx.x;
    int total = S * nheads * 32;
    if (idx >= total) return;
    int j = idx & 31;
    int rest = idx >> 5;
    int hh = rest % nheads;
    int s = rest / nheads;
    float inv = powf(10000.f, -(2.f * (float)j) / 64.f);
    float ph = (float)s * inv;
    float sn, cs;
    sincosf(ph, &sn, &cs);
    float* p = x + ((size_t)s * nheads + hh) * 64 + j;
    float x1 = p[0], x2 = p[32];
    p[0] = x1 * cs - x2 * sn;
    p[32] = x2 * cs + x1 * sn;
}

// ------------------------------ flash attention -----------------------------
__global__ void flash_kernel() {
    const float* Q = g_q;
    const float* Kg = g_k;
    const float* Vg = g_v;
    float* O = g_attn;
    extern __shared__ float sm[];
    float* Qs = sm;               // 64*64
    float* KT = sm + 4096;        // 64*65 (reused as P)
    float* Vs = KT + 64 * 65;     // 64*64
    int qt = blockIdx.x;
    int h = blockIdx.y;
    int kv = h >> 2;
    int tid = threadIdx.x;
    int tx = tid & 15, ty = tid >> 4;

    for (int e2 = tid; e2 < 4096; e2 += 256) {
        int r = e2 >> 6, d = e2 & 63;
        Qs[e2] = Q[(size_t)(qt * 64 + r) * H + h * 64 + d];
    }

    float m[4], l[4], acc[4][4];
#pragma unroll
    for (int i = 0; i < 4; ++i) {
        m[i] = -1e30f;
        l[i] = 0.f;
#pragma unroll
        for (int j = 0; j < 4; ++j) acc[i][j] = 0.f;
    }

    for (int kt = 0; kt <= qt; ++kt) {
        __syncthreads();
        for (int e2 = tid; e2 < 4096; e2 += 256) {
            int key = e2 >> 6, d = e2 & 63;
            KT[d * 65 + key] = Kg[(size_t)(kt * 64 + key) * (NKV * D) + kv * 64 + d];
            Vs[key * 64 + d] = Vg[(size_t)(kt * 64 + key) * (NKV * D) + kv * 64 + d];
        }
        __syncthreads();

        float s[4][4];
#pragma unroll
        for (int i = 0; i < 4; ++i)
#pragma unroll
            for (int j = 0; j < 4; ++j) s[i][j] = 0.f;
        for (int d = 0; d < 64; ++d) {
            float a[4], b[4];
#pragma unroll
            for (int i = 0; i < 4; ++i) a[i] = Qs[(ty + 16 * i) * 64 + d];
#pragma unroll
            for (int j = 0; j < 4; ++j) b[j] = KT[d * 65 + tx + 16 * j];
#pragma unroll
            for (int i = 0; i < 4; ++i)
#pragma unroll
                for (int j = 0; j < 4; ++j) s[i][j] += a[i] * b[j];
        }
#pragma unroll
        for (int i = 0; i < 4; ++i) {
            int qrow = qt * 64 + ty + 16 * i;
#pragma unroll
            for (int j = 0; j < 4; ++j) {
                int key = kt * 64 + tx + 16 * j;
                float sc = CAP * tanhf(s[i][j] * (MULT / CAP));
                s[i][j] = (key <= qrow) ? sc : -1e30f;
            }
        }
        __syncthreads();  // done reading KT as K; safe to overwrite with P
#pragma unroll
        for (int i = 0; i < 4; ++i) {
            float rm = s[i][0];
#pragma unroll
            for (int j = 1; j < 4; ++j) rm = fmaxf(rm, s[i][j]);
#pragma unroll
            for (int off = 8; off > 0; off >>= 1)
                rm = fmaxf(rm, __shfl_xor_sync(0xffffffffu, rm, off));
            float mn = fmaxf(m[i], rm);
            float scale = __expf(m[i] - mn);
            float rs = 0.f;
#pragma unroll
            for (int j = 0; j < 4; ++j) {
                float pv = __expf(s[i][j] - mn);
                s[i][j] = pv;
                rs += pv;
            }
#pragma unroll
            for (int off = 8; off > 0; off >>= 1)
                rs += __shfl_xor_sync(0xffffffffu, rs, off);
            l[i] = l[i] * scale + rs;
            m[i] = mn;
#pragma unroll
            for (int j = 0; j < 4; ++j) {
                acc[i][j] *= scale;
                KT[(ty + 16 * i) * 65 + tx + 16 * j] = s[i][j];
            }
        }
        __syncthreads();
        for (int key = 0; key < 64; ++key) {
            float a[4], b[4];
#pragma unroll
            for (int i = 0; i < 4; ++i) a[i] = KT[(ty + 16 * i) * 65 + key];
#pragma unroll
            for (int j = 0; j < 4; ++j) b[j] = Vs[key * 64 + tx + 16 * j];
#pragma unroll
            for (int i = 0; i < 4; ++i)
#pragma unroll
                for (int j = 0; j < 4; ++j) acc[i][j] += a[i] * b[j];
        }
    }
#pragma unroll
    for (int i = 0; i < 4; ++i) {
        float invl = 1.f / l[i];
#pragma unroll
        for (int j = 0; j < 4; ++j)
            O[(size_t)(qt * 64 + ty + 16 * i) * H + h * 64 + tx + 16 * j] =
                acc[i][j] * invl;
    }
}

// ------------------------------ router -------------------------------------
__global__ void router_kernel(const float* __restrict__ W,  // [H,E] harness ptr
                              float* __restrict__ logits_out) {
    const float* xf = g_xnorm;
    int t = blockIdx.x;
    int tid = threadIdx.x;
    int lane = tid & 31, warp = tid >> 5;
    float acc[E];
#pragma unroll
    for (int e = 0; e < E; ++e) acc[e] = 0.f;
    for (int hh = tid; hh < H; hh += 256) {
        float xv = xf[(size_t)t * H + hh];
        const float* wr = W + (size_t)hh * E;
#pragma unroll
        for (int e = 0; e < E; ++e) acc[e] += xv * wr[e];
    }
#pragma unroll
    for (int e = 0; e < E; ++e)
#pragma unroll
        for (int off = 16; off > 0; off >>= 1)
            acc[e] += __shfl_xor_sync(0xffffffffu, acc[e], off);
    __shared__ float wsum[8][E];
    __shared__ float logit[E];
    if (lane == 0)
#pragma unroll
        for (int e = 0; e < E; ++e) wsum[warp][e] = acc[e];
    __syncthreads();
    if (tid < E) {
        float s2 = 0.f;
        for (int w = 0; w < 8; ++w) s2 += wsum[w][tid];
        logit[tid] = s2;
        if (logits_out) logits_out[(size_t)t * E + tid] = s2;
    }
    __syncthreads();
    if (tid == 0) {
        float mx = logit[0];
        for (int e = 1; e < E; ++e) mx = fmaxf(mx, logit[e]);
        float ex[E], se = 0.f;
        for (int e = 0; e < E; ++e) {
            ex[e] = __expf(logit[e] - mx);
            se += ex[e];
        }
        int i0 = 0;
        for (int e = 1; e < E; ++e)
            if (ex[e] > ex[i0]) i0 = e;
        int i1 = (i0 == 0) ? 1 : 0;
        for (int e = 0; e < E; ++e)
            if (e != i0 && ex[e] > ex[i1]) i1 = e;
        float p0 = ex[i0] / se, p1 = ex[i1] / se;
        float inv2 = 1.f / (p0 + p1);
        g_topi[2 * t] = i0;
        g_topw[2 * t] = p0 * inv2;
        g_topi[2 * t + 1] = i1;
        g_topw[2 * t + 1] = p1 * inv2;
    }
}

// Deterministic serial plan: counts -> offsets -> stable placement. <<<1,1>>>
__global__ void plan_kernel() {
    int counts[E];
#pragma unroll
    for (int e = 0; e < E; ++e) counts[e] = 0;
    for (int a = 0; a < S * TOPK; ++a) counts[g_topi[a]]++;
    int off = 0;
    int cur[E];
    for (int e = 0; e < E; ++e) {
        g_offs[e] = off;
        cur[e] = off;
        off += counts[e];
    }
    g_offs[E] = off;
    for (int a = 0; a < S * TOPK; ++a) {
        int e = g_topi[a];
        int pos = cur[e]++;
        g_perm_token[pos] = a >> 1;
        g_tok2row[a] = pos;
    }
}

// ------------------------------ gelu * mul ----------------------------------
__global__ void gelu_mul_kernel() {
    int idx = blockIdx.x * blockDim.x + threadIdx.x;
    if (idx >= S * TOPK * F) return;
    float a = g_h1[idx];
    float b = g_hv[idx];
    float g = 0.5f * a * (1.f + erff(a * 0.70710678118654752f));
    g_h1[idx] = g * b;
}

// ------------------------------ launch --------------------------------------
extern "C" void kernel_launch(void* const* d_in, const int* in_sizes, int n_in,
                              void* d_out, int out_size) {
    const float* hs = (const float*)d_in[0];
    // d_in[1] = mask (causal tril) — computed analytically, unused
    const float* wq = (const float*)d_in[2];
    const float* wk = (const float*)d_in[3];
    const float* wv = (const float*)d_in[4];
    const float* wo = (const float*)d_in[5];
    const float* n1 = (const float*)d_in[6];
    const float* n2 = (const float*)d_in[7];
    // n3 at d_in[8], n4 at d_in[9]
    const float* n3 = (const float*)d_in[8];
    const float* n4 = (const float*)d_in[9];
    const float* router = (const float*)d_in[10];
    const float* we_w1 = (const float*)d_in[11];
    const float* we_v = (const float*)d_in[12];
    const float* we_d = (const float*)d_in[13];
    float* out = (float*)d_out;
    float* logits_out = (out_size >= S * H + S * E) ? out + (size_t)S * H : nullptr;

    cudaFuncSetAttribute(flash_kernel,
                         cudaFuncAttributeMaxDynamicSharedMemorySize, 49408);

    // 1. x = rmsnorm(hidden_states, n1) -> g_xnorm
    rmsnorm_kernel<<<S, 256>>>(hs, -1, n1, BUF_XNORM);

    // 2. q/k/v projections
    sgemm_kernel<<<dim3(H / 128, S / 128), 256>>>(BUF_XNORM, wq, BUF_Q, S, H, H);
    sgemm_kernel<<<dim3((NKV * D) / 128, S / 128), 256>>>(BUF_XNORM, wk, BUF_K, S, NKV * D, H);
    sgemm_kernel<<<dim3((NKV * D) / 128, S / 128), 256>>>(BUF_XNORM, wv, BUF_V, S, NKV * D, H);

    // 3. RoPE on q, k
    rope_kernel<<<(S * NH * 32 + 255) / 256, 256>>>(BUF_Q, NH);
    rope_kernel<<<(S * NKV * 32 + 255) / 256, 256>>>(BUF_K, NKV);

    // 4. attention -> g_attn
    flash_kernel<<<dim3(S / 64, NH), 256, 49408>>>();

    // 5. output proj + residual rmsnorm -> g_hidden
    sgemm_kernel<<<dim3(H / 128, S / 128), 256>>>(BUF_ATTN, wo, BUF_ATTNPROJ, S, H, H);
    add_rmsnorm_kernel<<<S, 256>>>(hs, BUF_ATTNPROJ, n2, BUF_HIDDEN);

    // 6. MoE input norm -> g_xnorm
    rmsnorm_kernel<<<S, 256>>>(nullptr, BUF_HIDDEN, n3, BUF_XNORM);

    // 7. routing + deterministic serial plan
    router_kernel<<<S, 256>>>(router, logits_out);
    plan_kernel<<<1, 1>>>();

    // 8. expert GEMMs (grouped, sparse dispatch: 2048 grouped rows total)
    sgemm_group_kernel<<<dim3(F / 128, 8, E), 256>>>(
        BUF_XNORM, we_w1, BUF_H1, F, H, (size_t)H * F, 1);
    sgemm_group_kernel<<<dim3(F / 128, 8, E), 256>>>(
        BUF_XNORM, we_v, BUF_HV, F, H, (size_t)H * F, 1);
    gelu_mul_kernel<<<(S * TOPK * F + 255) / 256, 256>>>();
    sgemm_group_kernel<<<dim3(H / 128, 8, E), 256>>>(
        BUF_H1, we_d, BUF_GOUT, H, F, (size_t)F * H, 0);

    // 9. combine + final residual rmsnorm, write output
    final_kernel<<<S, 256>>>(n4, out);
}

// round 5
// speedup vs baseline: 1.1662x; 1.1662x over previous
#include <cuda_runtime.h>
#include <math.h>

// ---------------------------------------------------------------------------
// Decoder layer, round 5: GEMMs on tf32 tensor cores with 3xTF32 split
// (hi/lo decomposition -> fp32-grade accuracy, kills routing-flip errors).
// Scratch buffers accessed ONLY as device symbols inside kernels (ATS trap).
// ---------------------------------------------------------------------------

#define S 1024
#define H 2048
#define NH 32
#define NKV 8
#define D 64
#define E 8
#define TOPK 2
#define F 4096
#define EPS 1e-5f
#define MULT 0.125f
#define CAP 30.0f

// ------------------------------ scratch (device globals) --------------------
__device__ float g_xnorm[S * H];
__device__ float g_q[S * NH * D];
__device__ float g_k[S * NKV * D];
__device__ float g_v[S * NKV * D];
__device__ float g_attn[S * H];
__device__ float g_attnproj[S * H];
__device__ float g_hidden[S * H];
__device__ float g_h1[S * TOPK * F];
__device__ float g_hv[S * TOPK * F];
__device__ float g_gout[S * TOPK * H];
__device__ int   g_topi[S * TOPK];
__device__ float g_topw[S * TOPK];
__device__ int   g_offs[E + 1];
__device__ int   g_perm_token[S * TOPK];
__device__ int   g_tok2row[S * TOPK];

#define BUF_XNORM 0
#define BUF_Q 1
#define BUF_K 2
#define BUF_V 3
#define BUF_ATTN 4
#define BUF_ATTNPROJ 5
#define BUF_HIDDEN 6
#define BUF_H1 7
#define BUF_HV 8
#define BUF_GOUT 9
__device__ __forceinline__ float* gbuf(int id) {
    switch (id) {
        case BUF_XNORM: return g_xnorm;
        case BUF_Q: return g_q;
        case BUF_K: return g_k;
        case BUF_V: return g_v;
        case BUF_ATTN: return g_attn;
        case BUF_ATTNPROJ: return g_attnproj;
        case BUF_HIDDEN: return g_hidden;
        case BUF_H1: return g_h1;
        case BUF_HV: return g_hv;
        default: return g_gout;
    }
}

// ------------------------------ tf32 helpers --------------------------------
__device__ __forceinline__ unsigned f2tf32(float x) {
    unsigned r;
    asm("cvt.rna.tf32.f32 %0, %1;" : "=r"(r) : "f"(x));
    return r;
}
// split x into hi (tf32) and lo (tf32 of remainder)
__device__ __forceinline__ void tf32split(float x, unsigned& hi, unsigned& lo) {
    hi = f2tf32(x);
    float rem = x - __uint_as_float(hi);
    lo = f2tf32(rem);
}

__device__ __forceinline__ void mma_tf32(float c[4], const unsigned a[4],
                                         const unsigned b[2]) {
    asm volatile(
        "mma.sync.aligned.m16n8k8.row.col.f32.tf32.tf32.f32 "
        "{%0,%1,%2,%3}, {%4,%5,%6,%7}, {%8,%9}, {%0,%1,%2,%3};"
        : "+f"(c[0]), "+f"(c[1]), "+f"(c[2]), "+f"(c[3])
        : "r"(a[0]), "r"(a[1]), "r"(a[2]), "r"(a[3]), "r"(b[0]), "r"(b[1]));
}

// ------------------------------ 3xtf32 tensor GEMM --------------------------
// 128x128 block tile, BK=16, 8 warps (2x4), warp tile 64x32.
struct GemmCtx {
    const float* A;
    const float* B;
    float* C;
    int N, K;
    int mBase;      // first output row of this block
    int rend;       // one past last valid output row
    int useGather;  // gather A rows through g_perm_token
};

__device__ __forceinline__ void tf32_gemm_body(const GemmCtx& g) {
    __shared__ unsigned AsH[128 * 20];
    __shared__ unsigned AsL[128 * 20];
    __shared__ unsigned BsH[16 * 132];
    __shared__ unsigned BsL[16 * 132];
    int tid = threadIdx.x;
    int lane = tid & 31, warp = tid >> 5;
    int wr = warp & 1, wc = warp >> 1;     // 2 x 4 warp grid
    int mW = wr * 64, nW = wc * 32;
    int gid = lane >> 2, tig = lane & 3;
    int nBase = blockIdx.x * 128;

    float acc[4][4][4];
#pragma unroll
    for (int mt = 0; mt < 4; ++mt)
#pragma unroll
        for (int nt = 0; nt < 4; ++nt)
#pragma unroll
            for (int r = 0; r < 4; ++r) acc[mt][nt][r] = 0.f;

    for (int k0 = 0; k0 < g.K; k0 += 16) {
        // stage A tile (128 x 16), split hi/lo
#pragma unroll
        for (int i = 0; i < 2; ++i) {
            int idx = tid + i * 256;
            int row = idx >> 2;
            int c4 = (idx & 3) * 4;
            int grow = g.mBase + row;
            float4 v = make_float4(0.f, 0.f, 0.f, 0.f);
            if (grow < g.rend) {
                int arow = g.useGather ? g_perm_token[grow] : grow;
                v = *(const float4*)&g.A[(size_t)arow * g.K + k0 + c4];
            }
            uint4 uh, ul;
            tf32split(v.x, uh.x, ul.x);
            tf32split(v.y, uh.y, ul.y);
            tf32split(v.z, uh.z, ul.z);
            tf32split(v.w, uh.w, ul.w);
            *(uint4*)&AsH[row * 20 + c4] = uh;
            *(uint4*)&AsL[row * 20 + c4] = ul;
        }
        // stage B tile (16 x 128), split hi/lo
#pragma unroll
        for (int i = 0; i < 2; ++i) {
            int idx = tid + i * 256;
            int row = idx >> 5;
            int c4 = (idx & 31) * 4;
            float4 v = *(const float4*)&g.B[(size_t)(k0 + row) * g.N + nBase + c4];
            uint4 uh, ul;
            tf32split(v.x, uh.x, ul.x);
            tf32split(v.y, uh.y, ul.y);
            tf32split(v.z, uh.z, ul.z);
            tf32split(v.w, uh.w, ul.w);
            *(uint4*)&BsH[row * 132 + c4] = uh;
            *(uint4*)&BsL[row * 132 + c4] = ul;
        }
        __syncthreads();

#pragma unroll
        for (int kk = 0; kk < 16; kk += 8) {
            unsigned aH[4][4], aL[4][4], bH[4][2], bL[4][2];
#pragma unroll
            for (int mt = 0; mt < 4; ++mt) {
                int r0 = (mW + mt * 16 + gid) * 20 + kk + tig;
                int r1 = r0 + 8 * 20;
                aH[mt][0] = AsH[r0];     aH[mt][1] = AsH[r1];
                aH[mt][2] = AsH[r0 + 4]; aH[mt][3] = AsH[r1 + 4];
                aL[mt][0] = AsL[r0];     aL[mt][1] = AsL[r1];
                aL[mt][2] = AsL[r0 + 4]; aL[mt][3] = AsL[r1 + 4];
            }
#pragma unroll
            for (int nt = 0; nt < 4; ++nt) {
                int c0 = (kk + tig) * 132 + nW + nt * 8 + gid;
                int c1 = c0 + 4 * 132;
                bH[nt][0] = BsH[c0]; bH[nt][1] = BsH[c1];
                bL[nt][0] = BsL[c0]; bL[nt][1] = BsL[c1];
            }
#pragma unroll
            for (int mt = 0; mt < 4; ++mt)
#pragma unroll
                for (int nt = 0; nt < 4; ++nt) {
                    mma_tf32(acc[mt][nt], aH[mt], bL[nt]);
                    mma_tf32(acc[mt][nt], aL[mt], bH[nt]);
                    mma_tf32(acc[mt][nt], aH[mt], bH[nt]);
                }
        }
        __syncthreads();
    }

    // store C
#pragma unroll
    for (int mt = 0; mt < 4; ++mt) {
        int r0 = g.mBase + mW + mt * 16 + gid;
#pragma unroll
        for (int nt = 0; nt < 4; ++nt) {
            int col = nBase + nW + nt * 8 + tig * 2;
            if (r0 < g.rend) {
                float2 v0 = make_float2(acc[mt][nt][0], acc[mt][nt][1]);
                *(float2*)&g.C[(size_t)r0 * g.N + col] = v0;
            }
            if (r0 + 8 < g.rend) {
                float2 v1 = make_float2(acc[mt][nt][2], acc[mt][nt][3]);
                *(float2*)&g.C[(size_t)(r0 + 8) * g.N + col] = v1;
            }
        }
    }
}

__global__ void tgemm_kernel(int aid, const float* __restrict__ B, int cid,
                             int M, int N, int K) {
    GemmCtx g;
    g.A = gbuf(aid);
    g.B = B;
    g.C = gbuf(cid);
    g.N = N; g.K = K;
    g.mBase = blockIdx.y * 128;
    g.rend = M;
    g.useGather = 0;
    tf32_gemm_body(g);
}

__global__ void tgemm_group_kernel(int aid, const float* __restrict__ Bfull,
                                   int cid, int N, int K, size_t Bstride,
                                   int use_gather) {
    int e = blockIdx.z;
    int rbeg = g_offs[e], rend = g_offs[e + 1];
    int mBase = rbeg + blockIdx.y * 128;
    if (mBase >= rend) return;
    GemmCtx g;
    g.A = gbuf(aid);
    g.B = Bfull + (size_t)e * Bstride;
    g.C = gbuf(cid);
    g.N = N; g.K = K;
    g.mBase = mBase;
    g.rend = rend;
    g.useGather = use_gather;
    tf32_gemm_body(g);
}

// ------------------------------ rmsnorm ------------------------------------
__global__ void rmsnorm_kernel(const float* __restrict__ xext, int xid,
                               const float* __restrict__ w, int yid) {
    const float* x = (xid < 0) ? xext : gbuf(xid);
    float* y = gbuf(yid);
    int row = blockIdx.x;
    int tid = threadIdx.x;
    const float* xr = x + (size_t)row * H;
    float ss = 0.f;
    float loc[8];
#pragma unroll
    for (int t = 0; t < 8; ++t) {
        float v = xr[tid + t * 256];
        loc[t] = v;
        ss += v * v;
    }
    __shared__ float red[256];
    red[tid] = ss;
    __syncthreads();
    for (int s2 = 128; s2 > 0; s2 >>= 1) {
        if (tid < s2) red[tid] += red[tid + s2];
        __syncthreads();
    }
    float inv = rsqrtf(red[0] / (float)H + EPS);
#pragma unroll
    for (int t = 0; t < 8; ++t) {
        int c = tid + t * 256;
        y[(size_t)row * H + c] = w[c] * loc[t] * inv;
    }
}

__global__ void add_rmsnorm_kernel(const float* __restrict__ residual, int xid,
                                   const float* __restrict__ w, int yid) {
    const float* x = gbuf(xid);
    float* y = gbuf(yid);
    int row = blockIdx.x;
    int tid = threadIdx.x;
    const float* xr = x + (size_t)row * H;
    float ss = 0.f;
    float loc[8];
#pragma unroll
    for (int t = 0; t < 8; ++t) {
        float v = xr[tid + t * 256];
        loc[t] = v;
        ss += v * v;
    }
    __shared__ float red[256];
    red[tid] = ss;
    __syncthreads();
    for (int s2 = 128; s2 > 0; s2 >>= 1) {
        if (tid < s2) red[tid] += red[tid + s2];
        __syncthreads();
    }
    float inv = rsqrtf(red[0] / (float)H + EPS);
#pragma unroll
    for (int t = 0; t < 8; ++t) {
        int c = tid + t * 256;
        y[(size_t)row * H + c] = residual[(size_t)row * H + c] + w[c] * loc[t] * inv;
    }
}

__global__ void final_kernel(const float* __restrict__ n4,
                             float* __restrict__ out) {
    int t = blockIdx.x;
    int tid = threadIdx.x;
    int r0 = g_tok2row[2 * t], r1 = g_tok2row[2 * t + 1];
    float w0 = g_topw[2 * t], w1 = g_topw[2 * t + 1];
    const float* a = g_gout + (size_t)r0 * H;
    const float* b = g_gout + (size_t)r1 * H;
    float ss = 0.f;
    float loc[8];
#pragma unroll
    for (int k = 0; k < 8; ++k) {
        int c = tid + k * 256;
        float v = w0 * a[c] + w1 * b[c];
        loc[k] = v;
        ss += v * v;
    }
    __shared__ float red[256];
    red[tid] = ss;
    __syncthreads();
    for (int s2 = 128; s2 > 0; s2 >>= 1) {
        if (tid < s2) red[tid] += red[tid + s2];
        __syncthreads();
    }
    float inv = rsqrtf(red[0] / (float)H + EPS);
#pragma unroll
    for (int k = 0; k < 8; ++k) {
        int c = tid + k * 256;
        out[(size_t)t * H + c] = g_hidden[(size_t)t * H + c] + n4[c] * loc[k] * inv;
    }
}

// ------------------------------ RoPE ---------------------------------------
__global__ void rope_kernel(int xid, int nheads) {
    float* x = gbuf(xid);
    int idx = blockIdx.x * blockDim.x + threadIdx.x;
    int total = S * nheads * 32;
    if (idx >= total) return;
    int j = idx & 31;
    int rest = idx >> 5;
    int hh = rest % nheads;
    int s = rest / nheads;
    float inv = powf(10000.f, -(2.f * (float)j) / 64.f);
    float ph = (float)s * inv;
    float sn, cs;
    sincosf(ph, &sn, &cs);
    float* p = x + ((size_t)s * nheads + hh) * 64 + j;
    float x1 = p[0], x2 = p[32];
    p[0] = x1 * cs - x2 * sn;
    p[32] = x2 * cs + x1 * sn;
}

// ------------------------------ flash attention -----------------------------
__global__ void flash_kernel() {
    const float* Q = g_q;
    const float* Kg = g_k;
    const float* Vg = g_v;
    float* O = g_attn;
    extern __shared__ float sm[];
    float* Qs = sm;               // 64*64
    float* KT = sm + 4096;        // 64*65 (reused as P)
    float* Vs = KT + 64 * 65;     // 64*64
    int qt = blockIdx.x;
    int h = blockIdx.y;
    int kv = h >> 2;
    int tid = threadIdx.x;
    int tx = tid & 15, ty = tid >> 4;

    for (int e2 = tid; e2 < 4096; e2 += 256) {
        int r = e2 >> 6, d = e2 & 63;
        Qs[e2] = Q[(size_t)(qt * 64 + r) * H + h * 64 + d];
    }

    float m[4], l[4], acc[4][4];
#pragma unroll
    for (int i = 0; i < 4; ++i) {
        m[i] = -1e30f;
        l[i] = 0.f;
#pragma unroll
        for (int j = 0; j < 4; ++j) acc[i][j] = 0.f;
    }

    for (int kt = 0; kt <= qt; ++kt) {
        __syncthreads();
        for (int e2 = tid; e2 < 4096; e2 += 256) {
            int key = e2 >> 6, d = e2 & 63;
            KT[d * 65 + key] = Kg[(size_t)(kt * 64 + key) * (NKV * D) + kv * 64 + d];
            Vs[key * 64 + d] = Vg[(size_t)(kt * 64 + key) * (NKV * D) + kv * 64 + d];
        }
        __syncthreads();

        float s[4][4];
#pragma unroll
        for (int i = 0; i < 4; ++i)
#pragma unroll
            for (int j = 0; j < 4; ++j) s[i][j] = 0.f;
        for (int d = 0; d < 64; ++d) {
            float a[4], b[4];
#pragma unroll
            for (int i = 0; i < 4; ++i) a[i] = Qs[(ty + 16 * i) * 64 + d];
#pragma unroll
            for (int j = 0; j < 4; ++j) b[j] = KT[d * 65 + tx + 16 * j];
#pragma unroll
            for (int i = 0; i < 4; ++i)
#pragma unroll
                for (int j = 0; j < 4; ++j) s[i][j] += a[i] * b[j];
        }
#pragma unroll
        for (int i = 0; i < 4; ++i) {
            int qrow = qt * 64 + ty + 16 * i;
#pragma unroll
            for (int j = 0; j < 4; ++j) {
                int key = kt * 64 + tx + 16 * j;
                float sc = CAP * tanhf(s[i][j] * (MULT / CAP));
                s[i][j] = (key <= qrow) ? sc : -1e30f;
            }
        }
        __syncthreads();
#pragma unroll
        for (int i = 0; i < 4; ++i) {
            float rm = s[i][0];
#pragma unroll
            for (int j = 1; j < 4; ++j) rm = fmaxf(rm, s[i][j]);
#pragma unroll
            for (int off = 8; off > 0; off >>= 1)
                rm = fmaxf(rm, __shfl_xor_sync(0xffffffffu, rm, off));
            float mn = fmaxf(m[i], rm);
            float scale = __expf(m[i] - mn);
            float rs = 0.f;
#pragma unroll
            for (int j = 0; j < 4; ++j) {
                float pv = __expf(s[i][j] - mn);
                s[i][j] = pv;
                rs += pv;
            }
#pragma unroll
            for (int off = 8; off > 0; off >>= 1)
                rs += __shfl_xor_sync(0xffffffffu, rs, off);
            l[i] = l[i] * scale + rs;
            m[i] = mn;
#pragma unroll
            for (int j = 0; j < 4; ++j) {
                acc[i][j] *= scale;
                KT[(ty + 16 * i) * 65 + tx + 16 * j] = s[i][j];
            }
        }
        __syncthreads();
        for (int key = 0; key < 64; ++key) {
            float a[4], b[4];
#pragma unroll
            for (int i = 0; i < 4; ++i) a[i] = KT[(ty + 16 * i) * 65 + key];
#pragma unroll
            for (int j = 0; j < 4; ++j) b[j] = Vs[key * 64 + tx + 16 * j];
#pragma unroll
            for (int i = 0; i < 4; ++i)
#pragma unroll
                for (int j = 0; j < 4; ++j) acc[i][j] += a[i] * b[j];
        }
    }
#pragma unroll
    for (int i = 0; i < 4; ++i) {
        float invl = 1.f / l[i];
#pragma unroll
        for (int j = 0; j < 4; ++j)
            O[(size_t)(qt * 64 + ty + 16 * i) * H + h * 64 + tx + 16 * j] =
                acc[i][j] * invl;
    }
}

// ------------------------------ router -------------------------------------
__global__ void router_kernel(const float* __restrict__ W,
                              float* __restrict__ logits_out) {
    const float* xf = g_xnorm;
    int t = blockIdx.x;
    int tid = threadIdx.x;
    int lane = tid & 31, warp = tid >> 5;
    float acc[E];
#pragma unroll
    for (int e = 0; e < E; ++e) acc[e] = 0.f;
    for (int hh = tid; hh < H; hh += 256) {
        float xv = xf[(size_t)t * H + hh];
        const float* wr = W + (size_t)hh * E;
#pragma unroll
        for (int e = 0; e < E; ++e) acc[e] += xv * wr[e];
    }
#pragma unroll
    for (int e = 0; e < E; ++e)
#pragma unroll
        for (int off = 16; off > 0; off >>= 1)
            acc[e] += __shfl_xor_sync(0xffffffffu, acc[e], off);
    __shared__ float wsum[8][E];
    __shared__ float logit[E];
    if (lane == 0)
#pragma unroll
        for (int e = 0; e < E; ++e) wsum[warp][e] = acc[e];
    __syncthreads();
    if (tid < E) {
        float s2 = 0.f;
        for (int w = 0; w < 8; ++w) s2 += wsum[w][tid];
        logit[tid] = s2;
        if (logits_out) logits_out[(size_t)t * E + tid] = s2;
    }
    __syncthreads();
    if (tid == 0) {
        float mx = logit[0];
        for (int e = 1; e < E; ++e) mx = fmaxf(mx, logit[e]);
        float ex[E], se = 0.f;
        for (int e = 0; e < E; ++e) {
            ex[e] = __expf(logit[e] - mx);
            se += ex[e];
        }
        int i0 = 0;
        for (int e = 1; e < E; ++e)
            if (ex[e] > ex[i0]) i0 = e;
        int i1 = (i0 == 0) ? 1 : 0;
        for (int e = 0; e < E; ++e)
            if (e != i0 && ex[e] > ex[i1]) i1 = e;
        float p0 = ex[i0] / se, p1 = ex[i1] / se;
        float inv2 = 1.f / (p0 + p1);
        g_topi[2 * t] = i0;
        g_topw[2 * t] = p0 * inv2;
        g_topi[2 * t + 1] = i1;
        g_topw[2 * t + 1] = p1 * inv2;
    }
}

__global__ void plan_kernel() {
    int counts[E];
#pragma unroll
    for (int e = 0; e < E; ++e) counts[e] = 0;
    for (int a = 0; a < S * TOPK; ++a) counts[g_topi[a]]++;
    int off = 0;
    int cur[E];
    for (int e = 0; e < E; ++e) {
        g_offs[e] = off;
        cur[e] = off;
        off += counts[e];
    }
    g_offs[E] = off;
    for (int a = 0; a < S * TOPK; ++a) {
        int e = g_topi[a];
        int pos = cur[e]++;
        g_perm_token[pos] = a >> 1;
        g_tok2row[a] = pos;
    }
}

// ------------------------------ gelu * mul ----------------------------------
__global__ void gelu_mul_kernel() {
    int idx = blockIdx.x * blockDim.x + threadIdx.x;
    if (idx >= S * TOPK * F) return;
    float a = g_h1[idx];
    float b = g_hv[idx];
    float g = 0.5f * a * (1.f + erff(a * 0.70710678118654752f));
    g_h1[idx] = g * b;
}

// ------------------------------ launch --------------------------------------
extern "C" void kernel_launch(void* const* d_in, const int* in_sizes, int n_in,
                              void* d_out, int out_size) {
    const float* hs = (const float*)d_in[0];
    const float* wq = (const float*)d_in[2];
    const float* wk = (const float*)d_in[3];
    const float* wv = (const float*)d_in[4];
    const float* wo = (const float*)d_in[5];
    const float* n1 = (const float*)d_in[6];
    const float* n2 = (const float*)d_in[7];
    const float* n3 = (const float*)d_in[8];
    const float* n4 = (const float*)d_in[9];
    const float* router = (const float*)d_in[10];
    const float* we_w1 = (const float*)d_in[11];
    const float* we_v = (const float*)d_in[12];
    const float* we_d = (const float*)d_in[13];
    float* out = (float*)d_out;
    float* logits_out = (out_size >= S * H + S * E) ? out + (size_t)S * H : nullptr;

    cudaFuncSetAttribute(flash_kernel,
                         cudaFuncAttributeMaxDynamicSharedMemorySize, 49408);

    // 1. x = rmsnorm(hidden_states, n1) -> g_xnorm
    rmsnorm_kernel<<<S, 256>>>(hs, -1, n1, BUF_XNORM);

    // 2. q/k/v projections (3xtf32 tensor cores)
    tgemm_kernel<<<dim3(H / 128, S / 128), 256>>>(BUF_XNORM, wq, BUF_Q, S, H, H);
    tgemm_kernel<<<dim3((NKV * D) / 128, S / 128), 256>>>(BUF_XNORM, wk, BUF_K, S, NKV * D, H);
    tgemm_kernel<<<dim3((NKV * D) / 128, S / 128), 256>>>(BUF_XNORM, wv, BUF_V, S, NKV * D, H);

    // 3. RoPE on q, k
    rope_kernel<<<(S * NH * 32 + 255) / 256, 256>>>(BUF_Q, NH);
    rope_kernel<<<(S * NKV * 32 + 255) / 256, 256>>>(BUF_K, NKV);

    // 4. attention -> g_attn
    flash_kernel<<<dim3(S / 64, NH), 256, 49408>>>();

    // 5. output proj + residual rmsnorm -> g_hidden
    tgemm_kernel<<<dim3(H / 128, S / 128), 256>>>(BUF_ATTN, wo, BUF_ATTNPROJ, S, H, H);
    add_rmsnorm_kernel<<<S, 256>>>(hs, BUF_ATTNPROJ, n2, BUF_HIDDEN);

    // 6. MoE input norm -> g_xnorm
    rmsnorm_kernel<<<S, 256>>>(nullptr, BUF_HIDDEN, n3, BUF_XNORM);

    // 7. routing + deterministic serial plan
    router_kernel<<<S, 256>>>(router, logits_out);
    plan_kernel<<<1, 1>>>();

    // 8. expert GEMMs (grouped, 3xtf32 tensor cores)
    tgemm_group_kernel<<<dim3(F / 128, 8, E), 256>>>(
        BUF_XNORM, we_w1, BUF_H1, F, H, (size_t)H * F, 1);
    tgemm_group_kernel<<<dim3(F / 128, 8, E), 256>>>(
        BUF_XNORM, we_v, BUF_HV, F, H, (size_t)H * F, 1);
    gelu_mul_kernel<<<(S * TOPK * F + 255) / 256, 256>>>();
    tgemm_group_kernel<<<dim3(H / 128, 8, E), 256>>>(
        BUF_H1, we_d, BUF_GOUT, H, F, (size_t)F * H, 0);

    // 9. combine + final residual rmsnorm, write output
    final_kernel<<<S, 256>>>(n4, out);
}

// round 6
// speedup vs baseline: 1.7074x; 1.4640x over previous
#include <cuda_runtime.h>
#include <math.h>

// ---------------------------------------------------------------------------
// Decoder layer, round 6: 3xtf32 tensor GEMMs with pre-split hi/lo planes,
// cp.async double buffering, 2 blocks/SM, fused QKV.
// Scratch accessed ONLY as device symbols inside kernels (ATS trap).
// ---------------------------------------------------------------------------

#define S 1024
#define H 2048
#define NH 32
#define NKV 8
#define D 64
#define E 8
#define TOPK 2
#define F 4096
#define EPS 1e-5f
#define MULT 0.125f
#define CAP 30.0f

// weight plane offsets (floats)
#define OFF_WQ  0u
#define OFF_WK  4194304u
#define OFF_WV  5242880u
#define OFF_WO  6291456u
#define OFF_W1  10485760ull
#define OFF_WEV 77594624ull
#define OFF_WD  144703488ull
#define W_TOTAL 211812352ull

// ------------------------------ scratch (device globals) --------------------
__device__ float g_wH[W_TOTAL];
__device__ float g_wL[W_TOTAL];
__device__ float g_xnH[S * H];
__device__ float g_xnL[S * H];
__device__ float g_xnorm[S * H];
__device__ float g_attnH[S * H];
__device__ float g_attnL[S * H];
__device__ float g_q[S * NH * D];
__device__ float g_k[S * NKV * D];
__device__ float g_v[S * NKV * D];
__device__ float g_attnproj[S * H];
__device__ float g_hidden[S * H];
__device__ float g_h1[S * TOPK * F];
__device__ float g_hv[S * TOPK * F];
__device__ float g_h1H[S * TOPK * F];
__device__ float g_h1L[S * TOPK * F];
__device__ float g_gout[S * TOPK * H];
__device__ int   g_topi[S * TOPK];
__device__ float g_topw[S * TOPK];
__device__ int   g_offs[E + 1];
__device__ int   g_perm_token[S * TOPK];
__device__ int   g_tok2row[S * TOPK];

// ------------------------------ tf32 helpers --------------------------------
__device__ __forceinline__ float f2tf32f(float x) {
    unsigned r;
    asm("cvt.rna.tf32.f32 %0, %1;" : "=r"(r) : "f"(x));
    return __uint_as_float(r);
}
__device__ __forceinline__ void tf32splitf(float x, float& hi, float& lo) {
    hi = f2tf32f(x);
    lo = f2tf32f(x - hi);
}
__device__ __forceinline__ void mma_tf32(float c[4], const unsigned a[4],
                                         const unsigned b[2]) {
    asm volatile(
        "mma.sync.aligned.m16n8k8.row.col.f32.tf32.tf32.f32 "
        "{%0,%1,%2,%3}, {%4,%5,%6,%7}, {%8,%9}, {%0,%1,%2,%3};"
        : "+f"(c[0]), "+f"(c[1]), "+f"(c[2]), "+f"(c[3])
        : "r"(a[0]), "r"(a[1]), "r"(a[2]), "r"(a[3]), "r"(b[0]), "r"(b[1]));
}
__device__ __forceinline__ void cpa16(unsigned dst, const void* src, bool valid) {
    int sz = valid ? 16 : 0;
    asm volatile("cp.async.ca.shared.global [%0], [%1], 16, %2;\n"
                 :: "r"(dst), "l"(src), "r"(sz));
}

// ------------------------------ weight split --------------------------------
__global__ void wsplit_kernel(const float* __restrict__ src, size_t dstOff,
                              int n4) {
    int i = blockIdx.x * blockDim.x + threadIdx.x;
    if (i >= n4) return;
    float4 v = *(const float4*)(src + (size_t)i * 4);
    float4 h, l;
    tf32splitf(v.x, h.x, l.x);
    tf32splitf(v.y, h.y, l.y);
    tf32splitf(v.z, h.z, l.z);
    tf32splitf(v.w, h.w, l.w);
    *(float4*)(g_wH + dstOff + (size_t)i * 4) = h;
    *(float4*)(g_wL + dstOff + (size_t)i * 4) = l;
}

// ------------------------------ GEMM body -----------------------------------
// 128x128 block, BK=16, 8 warps (2x4), warp tile 64x32, 3xtf32.
// smem per stage (floats): AH 2560 | AL 2560 | BH 2112 | BL 2112 = 9344
#define STG 9344
#define SMEM_BYTES (2 * STG * 4)

struct Ctx {
    const float *AH, *AL;   // [rows][K]
    const float *BH, *BL;   // [K][N]
    float* C;               // [rows][N]
    int N, K;
    int nBase;
    int mBase, rend;
    int useGather;
};

__device__ __forceinline__ void stage_tiles(const Ctx& g, float* sm, int sbuf,
                                            int k0, int tid) {
    unsigned base = (unsigned)__cvta_generic_to_shared(sm + sbuf * STG);
#pragma unroll
    for (int i = 0; i < 2; ++i) {
        int idx = tid + i * 256;
        int row = idx >> 2, c4 = (idx & 3) * 4;
        int grow = g.mBase + row;
        bool valid = grow < g.rend;
        int arow = valid ? (g.useGather ? g_perm_token[grow] : grow) : 0;
        size_t off = (size_t)arow * g.K + k0 + c4;
        unsigned d = base + (unsigned)(row * 20 + c4) * 4;
        cpa16(d, g.AH + off, valid);
        cpa16(d + 2560 * 4, g.AL + off, valid);
    }
#pragma unroll
    for (int i = 0; i < 2; ++i) {
        int idx = tid + i * 256;
        int row = idx >> 5, c4 = (idx & 31) * 4;
        size_t off = (size_t)(k0 + row) * g.N + g.nBase + c4;
        unsigned d = base + (unsigned)(5120 + row * 132 + c4) * 4;
        cpa16(d, g.BH + off, true);
        cpa16(d + 2112 * 4, g.BL + off, true);
    }
    asm volatile("cp.async.commit_group;" ::: "memory");
}

__device__ __forceinline__ void gemm_body(const Ctx& g) {
    extern __shared__ float sm[];
    int tid = threadIdx.x;
    int lane = tid & 31, warp = tid >> 5;
    int wr = warp & 1, wc = warp >> 1;
    int mW = wr * 64, nW = wc * 32;
    int gid = lane >> 2, tig = lane & 3;

    float acc[4][4][4];
#pragma unroll
    for (int mt = 0; mt < 4; ++mt)
#pragma unroll
        for (int nt = 0; nt < 4; ++nt)
#pragma unroll
            for (int r = 0; r < 4; ++r) acc[mt][nt][r] = 0.f;

    int niters = g.K / 16;
    stage_tiles(g, sm, 0, 0, tid);

    for (int it = 0; it < niters; ++it) {
        int cur = it & 1;
        if (it + 1 < niters) {
            stage_tiles(g, sm, cur ^ 1, (it + 1) * 16, tid);
            asm volatile("cp.async.wait_group 1;" ::: "memory");
        } else {
            asm volatile("cp.async.wait_group 0;" ::: "memory");
        }
        __syncthreads();

        const float* AHs = sm + cur * STG;
        const float* ALs = AHs + 2560;
        const float* BHs = AHs + 5120;
        const float* BLs = AHs + 7232;
#pragma unroll
        for (int kk = 0; kk < 16; kk += 8) {
            unsigned aH[4][4], aL[4][4], bH[4][2], bL[4][2];
#pragma unroll
            for (int mt = 0; mt < 4; ++mt) {
                int r0 = (mW + mt * 16 + gid) * 20 + kk + tig;
                int r1 = r0 + 160;
                aH[mt][0] = __float_as_uint(AHs[r0]);
                aH[mt][1] = __float_as_uint(AHs[r1]);
                aH[mt][2] = __float_as_uint(AHs[r0 + 4]);
                aH[mt][3] = __float_as_uint(AHs[r1 + 4]);
                aL[mt][0] = __float_as_uint(ALs[r0]);
                aL[mt][1] = __float_as_uint(ALs[r1]);
                aL[mt][2] = __float_as_uint(ALs[r0 + 4]);
                aL[mt][3] = __float_as_uint(ALs[r1 + 4]);
            }
#pragma unroll
            for (int nt = 0; nt < 4; ++nt) {
                int c0 = (kk + tig) * 132 + nW + nt * 8 + gid;
                int c1 = c0 + 528;
                bH[nt][0] = __float_as_uint(BHs[c0]);
                bH[nt][1] = __float_as_uint(BHs[c1]);
                bL[nt][0] = __float_as_uint(BLs[c0]);
                bL[nt][1] = __float_as_uint(BLs[c1]);
            }
#pragma unroll
            for (int mt = 0; mt < 4; ++mt)
#pragma unroll
                for (int nt = 0; nt < 4; ++nt) {
                    mma_tf32(acc[mt][nt], aH[mt], bL[nt]);
                    mma_tf32(acc[mt][nt], aL[mt], bH[nt]);
                    mma_tf32(acc[mt][nt], aH[mt], bH[nt]);
                }
        }
        __syncthreads();
    }

#pragma unroll
    for (int mt = 0; mt < 4; ++mt) {
        int r0 = g.mBase + mW + mt * 16 + gid;
#pragma unroll
        for (int nt = 0; nt < 4; ++nt) {
            int col = g.nBase + nW + nt * 8 + tig * 2;
            if (r0 < g.rend) {
                float2 v0 = make_float2(acc[mt][nt][0], acc[mt][nt][1]);
                *(float2*)&g.C[(size_t)r0 * g.N + col] = v0;
            }
            if (r0 + 8 < g.rend) {
                float2 v1 = make_float2(acc[mt][nt][2], acc[mt][nt][3]);
                *(float2*)&g.C[(size_t)(r0 + 8) * g.N + col] = v1;
            }
        }
    }
}

// fused q/k/v projection: grid (24, 8)
__global__ void __launch_bounds__(256, 2) tgemm_qkv_kernel() {
    int bx = blockIdx.x;
    Ctx g;
    g.AH = g_xnH; g.AL = g_xnL;
    g.K = H;
    g.mBase = blockIdx.y * 128;
    g.rend = S;
    g.useGather = 0;
    if (bx < 16) {
        g.BH = g_wH + OFF_WQ; g.BL = g_wL + OFF_WQ;
        g.C = g_q; g.N = 2048; g.nBase = bx * 128;
    } else if (bx < 20) {
        g.BH = g_wH + OFF_WK; g.BL = g_wL + OFF_WK;
        g.C = g_k; g.N = 512; g.nBase = (bx - 16) * 128;
    } else {
        g.BH = g_wH + OFF_WV; g.BL = g_wL + OFF_WV;
        g.C = g_v; g.N = 512; g.nBase = (bx - 20) * 128;
    }
    gemm_body(g);
}

// attention output projection: grid (16, 8)
__global__ void __launch_bounds__(256, 2) tgemm_wo_kernel() {
    Ctx g;
    g.AH = g_attnH; g.AL = g_attnL;
    g.BH = g_wH + OFF_WO; g.BL = g_wL + OFF_WO;
    g.C = g_attnproj;
    g.N = H; g.K = H;
    g.nBase = blockIdx.x * 128;
    g.mBase = blockIdx.y * 128;
    g.rend = S;
    g.useGather = 0;
    gemm_body(g);
}

// grouped expert GEMMs: which 0=w1->h1, 1=v->hv, 2=d->gout. grid (N/128, 8, E)
__global__ void __launch_bounds__(256, 2) tgemm_group_kernel(int which) {
    int e = blockIdx.z;
    int rbeg = g_offs[e], rend = g_offs[e + 1];
    int mBase = rbeg + blockIdx.y * 128;
    if (mBase >= rend) return;
    Ctx g;
    g.mBase = mBase;
    g.rend = rend;
    g.nBase = blockIdx.x * 128;
    if (which == 0) {
        g.AH = g_xnH; g.AL = g_xnL; g.useGather = 1;
        size_t off = OFF_W1 + (size_t)e * H * F;
        g.BH = g_wH + off; g.BL = g_wL + off;
        g.C = g_h1; g.N = F; g.K = H;
    } else if (which == 1) {
        g.AH = g_xnH; g.AL = g_xnL; g.useGather = 1;
        size_t off = OFF_WEV + (size_t)e * H * F;
        g.BH = g_wH + off; g.BL = g_wL + off;
        g.C = g_hv; g.N = F; g.K = H;
    } else {
        g.AH = g_h1H; g.AL = g_h1L; g.useGather = 0;
        size_t off = OFF_WD + (size_t)e * F * H;
        g.BH = g_wH + off; g.BL = g_wL + off;
        g.C = g_gout; g.N = H; g.K = F;
    }
    gemm_body(g);
}

// ------------------------------ rmsnorm -------------------------------------
// which: 0 = from ext (hs) -> planes only; 1 = from g_hidden -> planes + fp32
__global__ void rmsnorm_kernel(const float* __restrict__ xext, int which,
                               const float* __restrict__ w) {
    const float* x = (which == 0) ? xext : g_hidden;
    int row = blockIdx.x;
    int tid = threadIdx.x;
    const float* xr = x + (size_t)row * H;
    float ss = 0.f;
    float loc[8];
#pragma unroll
    for (int t = 0; t < 8; ++t) {
        float v = xr[tid + t * 256];
        loc[t] = v;
        ss += v * v;
    }
    __shared__ float red[256];
    red[tid] = ss;
    __syncthreads();
    for (int s2 = 128; s2 > 0; s2 >>= 1) {
        if (tid < s2) red[tid] += red[tid + s2];
        __syncthreads();
    }
    float inv = rsqrtf(red[0] / (float)H + EPS);
#pragma unroll
    for (int t = 0; t < 8; ++t) {
        int c = tid + t * 256;
        float y = w[c] * loc[t] * inv;
        float hi, lo;
        tf32splitf(y, hi, lo);
        g_xnH[(size_t)row * H + c] = hi;
        g_xnL[(size_t)row * H + c] = lo;
        if (which == 1) g_xnorm[(size_t)row * H + c] = y;
    }
}

__global__ void add_rmsnorm_kernel(const float* __restrict__ residual,
                                   const float* __restrict__ w) {
    int row = blockIdx.x;
    int tid = threadIdx.x;
    const float* xr = g_attnproj + (size_t)row * H;
    float ss = 0.f;
    float loc[8];
#pragma unroll
    for (int t = 0; t < 8; ++t) {
        float v = xr[tid + t * 256];
        loc[t] = v;
        ss += v * v;
    }
    __shared__ float red[256];
    red[tid] = ss;
    __syncthreads();
    for (int s2 = 128; s2 > 0; s2 >>= 1) {
        if (tid < s2) red[tid] += red[tid + s2];
        __syncthreads();
    }
    float inv = rsqrtf(red[0] / (float)H + EPS);
#pragma unroll
    for (int t = 0; t < 8; ++t) {
        int c = tid + t * 256;
        g_hidden[(size_t)row * H + c] =
            residual[(size_t)row * H + c] + w[c] * loc[t] * inv;
    }
}

__global__ void final_kernel(const float* __restrict__ n4,
                             float* __restrict__ out) {
    int t = blockIdx.x;
    int tid = threadIdx.x;
    int r0 = g_tok2row[2 * t], r1 = g_tok2row[2 * t + 1];
    float w0 = g_topw[2 * t], w1 = g_topw[2 * t + 1];
    const float* a = g_gout + (size_t)r0 * H;
    const float* b = g_gout + (size_t)r1 * H;
    float ss = 0.f;
    float loc[8];
#pragma unroll
    for (int k = 0; k < 8; ++k) {
        int c = tid + k * 256;
        float v = w0 * a[c] + w1 * b[c];
        loc[k] = v;
        ss += v * v;
    }
    __shared__ float red[256];
    red[tid] = ss;
    __syncthreads();
    for (int s2 = 128; s2 > 0; s2 >>= 1) {
        if (tid < s2) red[tid] += red[tid + s2];
        __syncthreads();
    }
    float inv = rsqrtf(red[0] / (float)H + EPS);
#pragma unroll
    for (int k = 0; k < 8; ++k) {
        int c = tid + k * 256;
        out[(size_t)t * H + c] = g_hidden[(size_t)t * H + c] + n4[c] * loc[k] * inv;
    }
}

// ------------------------------ RoPE ----------------------------------------
__global__ void rope_kernel(int isQ, int nheads) {
    float* x = isQ ? g_q : g_k;
    int idx = blockIdx.x * blockDim.x + threadIdx.x;
    int total = S * nheads * 32;
    if (idx >= total) return;
    int j = idx & 31;
    int rest = idx >> 5;
    int hh = rest % nheads;
    int s = rest / nheads;
    float inv = powf(10000.f, -(2.f * (float)j) / 64.f);
    float ph = (float)s * inv;
    float sn, cs;
    sincosf(ph, &sn, &cs);
    float* p = x + ((size_t)s * nheads + hh) * 64 + j;
    float x1 = p[0], x2 = p[32];
    p[0] = x1 * cs - x2 * sn;
    p[32] = x2 * cs + x1 * sn;
}

// ------------------------------ flash attention -----------------------------
__global__ void flash_kernel() {
    const float* Q = g_q;
    const float* Kg = g_k;
    const float* Vg = g_v;
    extern __shared__ float sm[];
    float* Qs = sm;               // 64*64
    float* KT = sm + 4096;        // 64*65 (reused as P)
    float* Vs = KT + 64 * 65;     // 64*64
    int qt = blockIdx.x;
    int h = blockIdx.y;
    int kv = h >> 2;
    int tid = threadIdx.x;
    int tx = tid & 15, ty = tid >> 4;

    for (int e2 = tid; e2 < 4096; e2 += 256) {
        int r = e2 >> 6, d = e2 & 63;
        Qs[e2] = Q[(size_t)(qt * 64 + r) * H + h * 64 + d];
    }

    float m[4], l[4], acc[4][4];
#pragma unroll
    for (int i = 0; i < 4; ++i) {
        m[i] = -1e30f;
        l[i] = 0.f;
#pragma unroll
        for (int j = 0; j < 4; ++j) acc[i][j] = 0.f;
    }

    for (int kt = 0; kt <= qt; ++kt) {
        __syncthreads();
        for (int e2 = tid; e2 < 4096; e2 += 256) {
            int key = e2 >> 6, d = e2 & 63;
            KT[d * 65 + key] = Kg[(size_t)(kt * 64 + key) * (NKV * D) + kv * 64 + d];
            Vs[key * 64 + d] = Vg[(size_t)(kt * 64 + key) * (NKV * D) + kv * 64 + d];
        }
        __syncthreads();

        float s[4][4];
#pragma unroll
        for (int i = 0; i < 4; ++i)
#pragma unroll
            for (int j = 0; j < 4; ++j) s[i][j] = 0.f;
        for (int d = 0; d < 64; ++d) {
            float a[4], b[4];
#pragma unroll
            for (int i = 0; i < 4; ++i) a[i] = Qs[(ty + 16 * i) * 64 + d];
#pragma unroll
            for (int j = 0; j < 4; ++j) b[j] = KT[d * 65 + tx + 16 * j];
#pragma unroll
            for (int i = 0; i < 4; ++i)
#pragma unroll
                for (int j = 0; j < 4; ++j) s[i][j] += a[i] * b[j];
        }
#pragma unroll
        for (int i = 0; i < 4; ++i) {
            int qrow = qt * 64 + ty + 16 * i;
#pragma unroll
            for (int j = 0; j < 4; ++j) {
                int key = kt * 64 + tx + 16 * j;
                float sc = CAP * tanhf(s[i][j] * (MULT / CAP));
                s[i][j] = (key <= qrow) ? sc : -1e30f;
            }
        }
        __syncthreads();
#pragma unroll
        for (int i = 0; i < 4; ++i) {
            float rm = s[i][0];
#pragma unroll
            for (int j = 1; j < 4; ++j) rm = fmaxf(rm, s[i][j]);
#pragma unroll
            for (int off = 8; off > 0; off >>= 1)
                rm = fmaxf(rm, __shfl_xor_sync(0xffffffffu, rm, off));
            float mn = fmaxf(m[i], rm);
            float scale = __expf(m[i] - mn);
            float rs = 0.f;
#pragma unroll
            for (int j = 0; j < 4; ++j) {
                float pv = __expf(s[i][j] - mn);
                s[i][j] = pv;
                rs += pv;
            }
#pragma unroll
            for (int off = 8; off > 0; off >>= 1)
                rs += __shfl_xor_sync(0xffffffffu, rs, off);
            l[i] = l[i] * scale + rs;
            m[i] = mn;
#pragma unroll
            for (int j = 0; j < 4; ++j) {
                acc[i][j] *= scale;
                KT[(ty + 16 * i) * 65 + tx + 16 * j] = s[i][j];
            }
        }
        __syncthreads();
        for (int key = 0; key < 64; ++key) {
            float a[4], b[4];
#pragma unroll
            for (int i = 0; i < 4; ++i) a[i] = KT[(ty + 16 * i) * 65 + key];
#pragma unroll
            for (int j = 0; j < 4; ++j) b[j] = Vs[key * 64 + tx + 16 * j];
#pragma unroll
            for (int i = 0; i < 4; ++i)
#pragma unroll
                for (int j = 0; j < 4; ++j) acc[i][j] += a[i] * b[j];
        }
    }
#pragma unroll
    for (int i = 0; i < 4; ++i) {
        float invl = 1.f / l[i];
#pragma unroll
        for (int j = 0; j < 4; ++j) {
            float o = acc[i][j] * invl;
            float hi, lo;
            tf32splitf(o, hi, lo);
            size_t idx = (size_t)(qt * 64 + ty + 16 * i) * H + h * 64 + tx + 16 * j;
            g_attnH[idx] = hi;
            g_attnL[idx] = lo;
        }
    }
}

// ------------------------------ router --------------------------------------
__global__ void router_kernel(const float* __restrict__ W,
                              float* __restrict__ logits_out) {
    const float* xf = g_xnorm;
    int t = blockIdx.x;
    int tid = threadIdx.x;
    int lane = tid & 31, warp = tid >> 5;
    float acc[E];
#pragma unroll
    for (int e = 0; e < E; ++e) acc[e] = 0.f;
    for (int hh = tid; hh < H; hh += 256) {
        float xv = xf[(size_t)t * H + hh];
        const float* wr = W + (size_t)hh * E;
#pragma unroll
        for (int e = 0; e < E; ++e) acc[e] += xv * wr[e];
    }
#pragma unroll
    for (int e = 0; e < E; ++e)
#pragma unroll
        for (int off = 16; off > 0; off >>= 1)
            acc[e] += __shfl_xor_sync(0xffffffffu, acc[e], off);
    __shared__ float wsum[8][E];
    __shared__ float logit[E];
    if (lane == 0)
#pragma unroll
        for (int e = 0; e < E; ++e) wsum[warp][e] = acc[e];
    __syncthreads();
    if (tid < E) {
        float s2 = 0.f;
        for (int w = 0; w < 8; ++w) s2 += wsum[w][tid];
        logit[tid] = s2;
        if (logits_out) logits_out[(size_t)t * E + tid] = s2;
    }
    __syncthreads();
    if (tid == 0) {
        float mx = logit[0];
        for (int e = 1; e < E; ++e) mx = fmaxf(mx, logit[e]);
        float ex[E], se = 0.f;
        for (int e = 0; e < E; ++e) {
            ex[e] = __expf(logit[e] - mx);
            se += ex[e];
        }
        int i0 = 0;
        for (int e = 1; e < E; ++e)
            if (ex[e] > ex[i0]) i0 = e;
        int i1 = (i0 == 0) ? 1 : 0;
        for (int e = 0; e < E; ++e)
            if (e != i0 && ex[e] > ex[i1]) i1 = e;
        float p0 = ex[i0] / se, p1 = ex[i1] / se;
        float inv2 = 1.f / (p0 + p1);
        g_topi[2 * t] = i0;
        g_topw[2 * t] = p0 * inv2;
        g_topi[2 * t + 1] = i1;
        g_topw[2 * t + 1] = p1 * inv2;
    }
}

__global__ void plan_kernel() {
    int counts[E];
#pragma unroll
    for (int e = 0; e < E; ++e) counts[e] = 0;
    for (int a = 0; a < S * TOPK; ++a) counts[g_topi[a]]++;
    int off = 0;
    int cur[E];
    for (int e = 0; e < E; ++e) {
        g_offs[e] = off;
        cur[e] = off;
        off += counts[e];
    }
    g_offs[E] = off;
    for (int a = 0; a < S * TOPK; ++a) {
        int e = g_topi[a];
        int pos = cur[e]++;
        g_perm_token[pos] = a >> 1;
        g_tok2row[a] = pos;
    }
}

// ------------------------------ gelu * mul ----------------------------------
__global__ void gelu_mul_kernel() {
    int idx = blockIdx.x * blockDim.x + threadIdx.x;
    if (idx >= S * TOPK * F) return;
    float a = g_h1[idx];
    float b = g_hv[idx];
    float g = 0.5f * a * (1.f + erff(a * 0.70710678118654752f));
    float y = g * b;
    float hi, lo;
    tf32splitf(y, hi, lo);
    g_h1H[idx] = hi;
    g_h1L[idx] = lo;
}

// ------------------------------ launch --------------------------------------
extern "C" void kernel_launch(void* const* d_in, const int* in_sizes, int n_in,
                              void* d_out, int out_size) {
    const float* hs = (const float*)d_in[0];
    const float* wq = (const float*)d_in[2];
    const float* wk = (const float*)d_in[3];
    const float* wv = (const float*)d_in[4];
    const float* wo = (const float*)d_in[5];
    const float* n1 = (const float*)d_in[6];
    const float* n2 = (const float*)d_in[7];
    const float* n3 = (const float*)d_in[8];
    const float* n4 = (const float*)d_in[9];
    const float* router = (const float*)d_in[10];
    const float* we_w1 = (const float*)d_in[11];
    const float* we_v = (const float*)d_in[12];
    const float* we_d = (const float*)d_in[13];
    float* out = (float*)d_out;
    float* logits_out = (out_size >= S * H + S * E) ? out + (size_t)S * H : nullptr;

    cudaFuncSetAttribute(flash_kernel,
                         cudaFuncAttributeMaxDynamicSharedMemorySize, 49408);
    cudaFuncSetAttribute(tgemm_qkv_kernel,
                         cudaFuncAttributeMaxDynamicSharedMemorySize, SMEM_BYTES);
    cudaFuncSetAttribute(tgemm_wo_kernel,
                         cudaFuncAttributeMaxDynamicSharedMemorySize, SMEM_BYTES);
    cudaFuncSetAttribute(tgemm_group_kernel,
                         cudaFuncAttributeMaxDynamicSharedMemorySize, SMEM_BYTES);

    // 0. split weights into tf32 hi/lo planes
    wsplit_kernel<<<4194304 / 1024, 256>>>(wq, OFF_WQ, 4194304 / 4);
    wsplit_kernel<<<1048576 / 1024, 256>>>(wk, OFF_WK, 1048576 / 4);
    wsplit_kernel<<<1048576 / 1024, 256>>>(wv, OFF_WV, 1048576 / 4);
    wsplit_kernel<<<4194304 / 1024, 256>>>(wo, OFF_WO, 4194304 / 4);
    wsplit_kernel<<<67108864 / 1024, 256>>>(we_w1, OFF_W1, 67108864 / 4);
    wsplit_kernel<<<67108864 / 1024, 256>>>(we_v, OFF_WEV, 67108864 / 4);
    wsplit_kernel<<<67108864 / 1024, 256>>>(we_d, OFF_WD, 67108864 / 4);

    // 1. x = rmsnorm(hs, n1) -> xn planes
    rmsnorm_kernel<<<S, 256>>>(hs, 0, n1);

    // 2. fused q/k/v projection
    tgemm_qkv_kernel<<<dim3(24, 8), 256, SMEM_BYTES>>>();

    // 3. RoPE
    rope_kernel<<<(S * NH * 32 + 255) / 256, 256>>>(1, NH);
    rope_kernel<<<(S * NKV * 32 + 255) / 256, 256>>>(0, NKV);

    // 4. attention -> attn planes
    flash_kernel<<<dim3(S / 64, NH), 256, 49408>>>();

    // 5. output proj + residual rmsnorm -> g_hidden
    tgemm_wo_kernel<<<dim3(16, 8), 256, SMEM_BYTES>>>();
    add_rmsnorm_kernel<<<S, 256>>>(hs, n2);

    // 6. MoE input norm -> xn planes + g_xnorm fp32 (router)
    rmsnorm_kernel<<<S, 256>>>(nullptr, 1, n3);

    // 7. routing + plan
    router_kernel<<<S, 256>>>(router, logits_out);
    plan_kernel<<<1, 1>>>();

    // 8. expert GEMMs
    tgemm_group_kernel<<<dim3(F / 128, 8, E), 256, SMEM_BYTES>>>(0);
    tgemm_group_kernel<<<dim3(F / 128, 8, E), 256, SMEM_BYTES>>>(1);
    gelu_mul_kernel<<<(S * TOPK * F + 255) / 256, 256>>>();
    tgemm_group_kernel<<<dim3(H / 128, 8, E), 256, SMEM_BYTES>>>(2);

    // 9. combine + final residual rmsnorm
    final_kernel<<<S, 256>>>(n4, out);
}

// round 7
// speedup vs baseline: 1.9593x; 1.1476x over previous
#include <cuda_runtime.h>
#include <math.h>

// ---------------------------------------------------------------------------
// Decoder layer, round 7: 3xtf32 GEMMs with raw-fp32 weight staging +
// in-register hi/lo split (no persistent weight planes, no wsplit pass),
// gelu*mul fused into the hv-GEMM epilogue.
// Scratch accessed ONLY as device symbols inside kernels (ATS trap).
// ---------------------------------------------------------------------------

#define S 1024
#define H 2048
#define NH 32
#define NKV 8
#define D 64
#define E 8
#define TOPK 2
#define F 4096
#define EPS 1e-5f
#define MULT 0.125f
#define CAP 30.0f

// ------------------------------ scratch (device globals) --------------------
__device__ float g_xnH[S * H];
__device__ float g_xnL[S * H];
__device__ float g_xnorm[S * H];
__device__ float g_attnH[S * H];
__device__ float g_attnL[S * H];
__device__ float g_q[S * NH * D];
__device__ float g_k[S * NKV * D];
__device__ float g_v[S * NKV * D];
__device__ float g_attnproj[S * H];
__device__ float g_hidden[S * H];
__device__ float g_h1[S * TOPK * F];
__device__ float g_h1H[S * TOPK * F];
__device__ float g_h1L[S * TOPK * F];
__device__ float g_gout[S * TOPK * H];
__device__ int   g_topi[S * TOPK];
__device__ float g_topw[S * TOPK];
__device__ int   g_offs[E + 1];
__device__ int   g_perm_token[S * TOPK];
__device__ int   g_tok2row[S * TOPK];

// ------------------------------ tf32 helpers --------------------------------
__device__ __forceinline__ float f2tf32f(float x) {
    unsigned r;
    asm("cvt.rna.tf32.f32 %0, %1;" : "=r"(r) : "f"(x));
    return __uint_as_float(r);
}
__device__ __forceinline__ void tf32splitf(float x, float& hi, float& lo) {
    hi = f2tf32f(x);
    lo = f2tf32f(x - hi);
}
__device__ __forceinline__ void tf32splitu(float x, unsigned& hi, unsigned& lo) {
    float h = f2tf32f(x);
    hi = __float_as_uint(h);
    lo = __float_as_uint(f2tf32f(x - h));
}
__device__ __forceinline__ void mma_tf32(float c[4], const unsigned a[4],
                                         const unsigned b[2]) {
    asm volatile(
        "mma.sync.aligned.m16n8k8.row.col.f32.tf32.tf32.f32 "
        "{%0,%1,%2,%3}, {%4,%5,%6,%7}, {%8,%9}, {%0,%1,%2,%3};"
        : "+f"(c[0]), "+f"(c[1]), "+f"(c[2]), "+f"(c[3])
        : "r"(a[0]), "r"(a[1]), "r"(a[2]), "r"(a[3]), "r"(b[0]), "r"(b[1]));
}
__device__ __forceinline__ void cpa16(unsigned dst, const void* src, bool valid) {
    int sz = valid ? 16 : 0;
    asm volatile("cp.async.ca.shared.global [%0], [%1], 16, %2;\n"
                 :: "r"(dst), "l"(src), "r"(sz));
}

// ------------------------------ GEMM body -----------------------------------
// 128x128 block, BK=16, 8 warps (2x4), warp tile 64x32, 3xtf32.
// smem/stage (floats): AH 2560 | AL 2560 | Braw 2112 = 7232
#define STG 7232
#define SMEM_BYTES (2 * STG * 4)

struct Ctx {
    const float *AH, *AL;   // activation planes [rows][K]
    const float *B;         // raw fp32 weights [K][N]
    float* C;
    int N, K;
    int nBase;
    int mBase, rend;
    int useGather;
    int epi;   // 0 = plain store, 1 = gelu(h1)*acc -> split planes
};

__device__ __forceinline__ void stage_tiles(const Ctx& g, float* sm, int sbuf,
                                            int k0, int tid) {
    unsigned base = (unsigned)__cvta_generic_to_shared(sm + sbuf * STG);
#pragma unroll
    for (int i = 0; i < 2; ++i) {
        int idx = tid + i * 256;
        int row = idx >> 2, c4 = (idx & 3) * 4;
        int grow = g.mBase + row;
        bool valid = grow < g.rend;
        int arow = valid ? (g.useGather ? g_perm_token[grow] : grow) : 0;
        size_t off = (size_t)arow * g.K + k0 + c4;
        unsigned d = base + (unsigned)(row * 20 + c4) * 4;
        cpa16(d, g.AH + off, valid);
        cpa16(d + 2560 * 4, g.AL + off, valid);
    }
#pragma unroll
    for (int i = 0; i < 2; ++i) {
        int idx = tid + i * 256;
        int row = idx >> 5, c4 = (idx & 31) * 4;
        size_t off = (size_t)(k0 + row) * g.N + g.nBase + c4;
        unsigned d = base + (unsigned)(5120 + row * 132 + c4) * 4;
        cpa16(d, g.B + off, true);
    }
    asm volatile("cp.async.commit_group;" ::: "memory");
}

__device__ __forceinline__ void gemm_body(const Ctx& g) {
    extern __shared__ float sm[];
    int tid = threadIdx.x;
    int lane = tid & 31, warp = tid >> 5;
    int wr = warp & 1, wc = warp >> 1;
    int mW = wr * 64, nW = wc * 32;
    int gid = lane >> 2, tig = lane & 3;

    float acc[4][4][4];
#pragma unroll
    for (int mt = 0; mt < 4; ++mt)
#pragma unroll
        for (int nt = 0; nt < 4; ++nt)
#pragma unroll
            for (int r = 0; r < 4; ++r) acc[mt][nt][r] = 0.f;

    int niters = g.K / 16;
    stage_tiles(g, sm, 0, 0, tid);

    for (int it = 0; it < niters; ++it) {
        int cur = it & 1;
        if (it + 1 < niters) {
            stage_tiles(g, sm, cur ^ 1, (it + 1) * 16, tid);
            asm volatile("cp.async.wait_group 1;" ::: "memory");
        } else {
            asm volatile("cp.async.wait_group 0;" ::: "memory");
        }
        __syncthreads();

        const float* AHs = sm + cur * STG;
        const float* ALs = AHs + 2560;
        const float* Bs = AHs + 5120;
#pragma unroll
        for (int kk = 0; kk < 16; kk += 8) {
            unsigned aH[4][4], aL[4][4], bH[4][2], bL[4][2];
#pragma unroll
            for (int mt = 0; mt < 4; ++mt) {
                int r0 = (mW + mt * 16 + gid) * 20 + kk + tig;
                int r1 = r0 + 160;
                aH[mt][0] = __float_as_uint(AHs[r0]);
                aH[mt][1] = __float_as_uint(AHs[r1]);
                aH[mt][2] = __float_as_uint(AHs[r0 + 4]);
                aH[mt][3] = __float_as_uint(AHs[r1 + 4]);
                aL[mt][0] = __float_as_uint(ALs[r0]);
                aL[mt][1] = __float_as_uint(ALs[r1]);
                aL[mt][2] = __float_as_uint(ALs[r0 + 4]);
                aL[mt][3] = __float_as_uint(ALs[r1 + 4]);
            }
#pragma unroll
            for (int nt = 0; nt < 4; ++nt) {
                int c0 = (kk + tig) * 132 + nW + nt * 8 + gid;
                int c1 = c0 + 528;
                tf32splitu(Bs[c0], bH[nt][0], bL[nt][0]);
                tf32splitu(Bs[c1], bH[nt][1], bL[nt][1]);
            }
#pragma unroll
            for (int mt = 0; mt < 4; ++mt)
#pragma unroll
                for (int nt = 0; nt < 4; ++nt) {
                    mma_tf32(acc[mt][nt], aH[mt], bL[nt]);
                    mma_tf32(acc[mt][nt], aL[mt], bH[nt]);
                    mma_tf32(acc[mt][nt], aH[mt], bH[nt]);
                }
        }
        __syncthreads();
    }

#pragma unroll
    for (int mt = 0; mt < 4; ++mt) {
#pragma unroll
        for (int half = 0; half < 2; ++half) {
            int r0 = g.mBase + mW + mt * 16 + gid + half * 8;
            if (r0 >= g.rend) continue;
#pragma unroll
            for (int nt = 0; nt < 4; ++nt) {
                int col = g.nBase + nW + nt * 8 + tig * 2;
                float v0 = acc[mt][nt][half * 2 + 0];
                float v1 = acc[mt][nt][half * 2 + 1];
                size_t idx = (size_t)r0 * g.N + col;
                if (g.epi == 0) {
                    *(float2*)&g.C[idx] = make_float2(v0, v1);
                } else {
                    // gelu(h1) * acc -> split planes
                    float a0 = g_h1[idx], a1 = g_h1[idx + 1];
                    float ge0 = 0.5f * a0 * (1.f + erff(a0 * 0.7071067811865475f));
                    float ge1 = 0.5f * a1 * (1.f + erff(a1 * 0.7071067811865475f));
                    float y0 = ge0 * v0, y1 = ge1 * v1;
                    float h0, l0, h1v, l1;
                    tf32splitf(y0, h0, l0);
                    tf32splitf(y1, h1v, l1);
                    *(float2*)&g_h1H[idx] = make_float2(h0, h1v);
                    *(float2*)&g_h1L[idx] = make_float2(l0, l1);
                }
            }
        }
    }
}

// fused q/k/v projection: grid (24, 8)
__global__ void __launch_bounds__(256, 2) tgemm_qkv_kernel(
    const float* __restrict__ wq, const float* __restrict__ wk,
    const float* __restrict__ wv) {
    int bx = blockIdx.x;
    Ctx g;
    g.AH = g_xnH; g.AL = g_xnL;
    g.K = H;
    g.mBase = blockIdx.y * 128;
    g.rend = S;
    g.useGather = 0;
    g.epi = 0;
    if (bx < 16) {
        g.B = wq; g.C = g_q; g.N = 2048; g.nBase = bx * 128;
    } else if (bx < 20) {
        g.B = wk; g.C = g_k; g.N = 512; g.nBase = (bx - 16) * 128;
    } else {
        g.B = wv; g.C = g_v; g.N = 512; g.nBase = (bx - 20) * 128;
    }
    gemm_body(g);
}

// attention output projection: grid (16, 8)
__global__ void __launch_bounds__(256, 2) tgemm_wo_kernel(
    const float* __restrict__ wo) {
    Ctx g;
    g.AH = g_attnH; g.AL = g_attnL;
    g.B = wo;
    g.C = g_attnproj;
    g.N = H; g.K = H;
    g.nBase = blockIdx.x * 128;
    g.mBase = blockIdx.y * 128;
    g.rend = S;
    g.useGather = 0;
    g.epi = 0;
    gemm_body(g);
}

// grouped expert GEMMs: which 0=w1->h1, 1=v->gelu*h1 planes, 2=d->gout
__global__ void __launch_bounds__(256, 2) tgemm_group_kernel(
    const float* __restrict__ W, int which) {
    int e = blockIdx.z;
    int rbeg = g_offs[e], rend = g_offs[e + 1];
    int mBase = rbeg + blockIdx.y * 128;
    if (mBase >= rend) return;
    Ctx g;
    g.mBase = mBase;
    g.rend = rend;
    g.nBase = blockIdx.x * 128;
    if (which == 0) {
        g.AH = g_xnH; g.AL = g_xnL; g.useGather = 1; g.epi = 0;
        g.B = W + (size_t)e * H * F;
        g.C = g_h1; g.N = F; g.K = H;
    } else if (which == 1) {
        g.AH = g_xnH; g.AL = g_xnL; g.useGather = 1; g.epi = 1;
        g.B = W + (size_t)e * H * F;
        g.C = g_h1; g.N = F; g.K = H;  // C unused in epi=1 path (planes written)
    } else {
        g.AH = g_h1H; g.AL = g_h1L; g.useGather = 0; g.epi = 0;
        g.B = W + (size_t)e * F * H;
        g.C = g_gout; g.N = H; g.K = F;
    }
    gemm_body(g);
}

// ------------------------------ rmsnorm -------------------------------------
__global__ void rmsnorm_kernel(const float* __restrict__ xext, int which,
                               const float* __restrict__ w) {
    const float* x = (which == 0) ? xext : g_hidden;
    int row = blockIdx.x;
    int tid = threadIdx.x;
    const float* xr = x + (size_t)row * H;
    float ss = 0.f;
    float loc[8];
#pragma unroll
    for (int t = 0; t < 8; ++t) {
        float v = xr[tid + t * 256];
        loc[t] = v;
        ss += v * v;
    }
    __shared__ float red[256];
    red[tid] = ss;
    __syncthreads();
    for (int s2 = 128; s2 > 0; s2 >>= 1) {
        if (tid < s2) red[tid] += red[tid + s2];
        __syncthreads();
    }
    float inv = rsqrtf(red[0] / (float)H + EPS);
#pragma unroll
    for (int t = 0; t < 8; ++t) {
        int c = tid + t * 256;
        float y = w[c] * loc[t] * inv;
        float hi, lo;
        tf32splitf(y, hi, lo);
        g_xnH[(size_t)row * H + c] = hi;
        g_xnL[(size_t)row * H + c] = lo;
        if (which == 1) g_xnorm[(size_t)row * H + c] = y;
    }
}

__global__ void add_rmsnorm_kernel(const float* __restrict__ residual,
                                   const float* __restrict__ w) {
    int row = blockIdx.x;
    int tid = threadIdx.x;
    const float* xr = g_attnproj + (size_t)row * H;
    float ss = 0.f;
    float loc[8];
#pragma unroll
    for (int t = 0; t < 8; ++t) {
        float v = xr[tid + t * 256];
        loc[t] = v;
        ss += v * v;
    }
    __shared__ float red[256];
    red[tid] = ss;
    __syncthreads();
    for (int s2 = 128; s2 > 0; s2 >>= 1) {
        if (tid < s2) red[tid] += red[tid + s2];
        __syncthreads();
    }
    float inv = rsqrtf(red[0] / (float)H + EPS);
#pragma unroll
    for (int t = 0; t < 8; ++t) {
        int c = tid + t * 256;
        g_hidden[(size_t)row * H + c] =
            residual[(size_t)row * H + c] + w[c] * loc[t] * inv;
    }
}

__global__ void final_kernel(const float* __restrict__ n4,
                             float* __restrict__ out) {
    int t = blockIdx.x;
    int tid = threadIdx.x;
    int r0 = g_tok2row[2 * t], r1 = g_tok2row[2 * t + 1];
    float w0 = g_topw[2 * t], w1 = g_topw[2 * t + 1];
    const float* a = g_gout + (size_t)r0 * H;
    const float* b = g_gout + (size_t)r1 * H;
    float ss = 0.f;
    float loc[8];
#pragma unroll
    for (int k = 0; k < 8; ++k) {
        int c = tid + k * 256;
        float v = w0 * a[c] + w1 * b[c];
        loc[k] = v;
        ss += v * v;
    }
    __shared__ float red[256];
    red[tid] = ss;
    __syncthreads();
    for (int s2 = 128; s2 > 0; s2 >>= 1) {
        if (tid < s2) red[tid] += red[tid + s2];
        __syncthreads();
    }
    float inv = rsqrtf(red[0] / (float)H + EPS);
#pragma unroll
    for (int k = 0; k < 8; ++k) {
        int c = tid + k * 256;
        out[(size_t)t * H + c] = g_hidden[(size_t)t * H + c] + n4[c] * loc[k] * inv;
    }
}

// ------------------------------ RoPE ----------------------------------------
__global__ void rope_kernel(int isQ, int nheads) {
    float* x = isQ ? g_q : g_k;
    int idx = blockIdx.x * blockDim.x + threadIdx.x;
    int total = S * nheads * 32;
    if (idx >= total) return;
    int j = idx & 31;
    int rest = idx >> 5;
    int hh = rest % nheads;
    int s = rest / nheads;
    float inv = powf(10000.f, -(2.f * (float)j) / 64.f);
    float ph = (float)s * inv;
    float sn, cs;
    sincosf(ph, &sn, &cs);
    float* p = x + ((size_t)s * nheads + hh) * 64 + j;
    float x1 = p[0], x2 = p[32];
    p[0] = x1 * cs - x2 * sn;
    p[32] = x2 * cs + x1 * sn;
}

// ------------------------------ flash attention -----------------------------
__global__ void flash_kernel() {
    const float* Q = g_q;
    const float* Kg = g_k;
    const float* Vg = g_v;
    extern __shared__ float sm[];
    float* Qs = sm;               // 64*64
    float* KT = sm + 4096;        // 64*65 (reused as P)
    float* Vs = KT + 64 * 65;     // 64*64
    int qt = blockIdx.x;
    int h = blockIdx.y;
    int kv = h >> 2;
    int tid = threadIdx.x;
    int tx = tid & 15, ty = tid >> 4;

    for (int e2 = tid; e2 < 4096; e2 += 256) {
        int r = e2 >> 6, d = e2 & 63;
        Qs[e2] = Q[(size_t)(qt * 64 + r) * H + h * 64 + d];
    }

    float m[4], l[4], acc[4][4];
#pragma unroll
    for (int i = 0; i < 4; ++i) {
        m[i] = -1e30f;
        l[i] = 0.f;
#pragma unroll
        for (int j = 0; j < 4; ++j) acc[i][j] = 0.f;
    }

    for (int kt = 0; kt <= qt; ++kt) {
        __syncthreads();
        for (int e2 = tid; e2 < 4096; e2 += 256) {
            int key = e2 >> 6, d = e2 & 63;
            KT[d * 65 + key] = Kg[(size_t)(kt * 64 + key) * (NKV * D) + kv * 64 + d];
            Vs[key * 64 + d] = Vg[(size_t)(kt * 64 + key) * (NKV * D) + kv * 64 + d];
        }
        __syncthreads();

        float s[4][4];
#pragma unroll
        for (int i = 0; i < 4; ++i)
#pragma unroll
            for (int j = 0; j < 4; ++j) s[i][j] = 0.f;
        for (int d = 0; d < 64; ++d) {
            float a[4], b[4];
#pragma unroll
            for (int i = 0; i < 4; ++i) a[i] = Qs[(ty + 16 * i) * 64 + d];
#pragma unroll
            for (int j = 0; j < 4; ++j) b[j] = KT[d * 65 + tx + 16 * j];
#pragma unroll
            for (int i = 0; i < 4; ++i)
#pragma unroll
                for (int j = 0; j < 4; ++j) s[i][j] += a[i] * b[j];
        }
#pragma unroll
        for (int i = 0; i < 4; ++i) {
            int qrow = qt * 64 + ty + 16 * i;
#pragma unroll
            for (int j = 0; j < 4; ++j) {
                int key = kt * 64 + tx + 16 * j;
                float sc = CAP * tanhf(s[i][j] * (MULT / CAP));
                s[i][j] = (key <= qrow) ? sc : -1e30f;
            }
        }
        __syncthreads();
#pragma unroll
        for (int i = 0; i < 4; ++i) {
            float rm = s[i][0];
#pragma unroll
            for (int j = 1; j < 4; ++j) rm = fmaxf(rm, s[i][j]);
#pragma unroll
            for (int off = 8; off > 0; off >>= 1)
                rm = fmaxf(rm, __shfl_xor_sync(0xffffffffu, rm, off));
            float mn = fmaxf(m[i], rm);
            float scale = __expf(m[i] - mn);
            float rs = 0.f;
#pragma unroll
            for (int j = 0; j < 4; ++j) {
                float pv = __expf(s[i][j] - mn);
                s[i][j] = pv;
                rs += pv;
            }
#pragma unroll
            for (int off = 8; off > 0; off >>= 1)
                rs += __shfl_xor_sync(0xffffffffu, rs, off);
            l[i] = l[i] * scale + rs;
            m[i] = mn;
#pragma unroll
            for (int j = 0; j < 4; ++j) {
                acc[i][j] *= scale;
                KT[(ty + 16 * i) * 65 + tx + 16 * j] = s[i][j];
            }
        }
        __syncthreads();
        for (int key = 0; key < 64; ++key) {
            float a[4], b[4];
#pragma unroll
            for (int i = 0; i < 4; ++i) a[i] = KT[(ty + 16 * i) * 65 + key];
#pragma unroll
            for (int j = 0; j < 4; ++j) b[j] = Vs[key * 64 + tx + 16 * j];
#pragma unroll
            for (int i = 0; i < 4; ++i)
#pragma unroll
                for (int j = 0; j < 4; ++j) acc[i][j] += a[i] * b[j];
        }
    }
#pragma unroll
    for (int i = 0; i < 4; ++i) {
        float invl = 1.f / l[i];
#pragma unroll
        for (int j = 0; j < 4; ++j) {
            float o = acc[i][j] * invl;
            float hi, lo;
            tf32splitf(o, hi, lo);
            size_t idx = (size_t)(qt * 64 + ty + 16 * i) * H + h * 64 + tx + 16 * j;
            g_attnH[idx] = hi;
            g_attnL[idx] = lo;
        }
    }
}

// ------------------------------ router --------------------------------------
__global__ void router_kernel(const float* __restrict__ W,
                              float* __restrict__ logits_out) {
    const float* xf = g_xnorm;
    int t = blockIdx.x;
    int tid = threadIdx.x;
    int lane = tid & 31, warp = tid >> 5;
    float acc[E];
#pragma unroll
    for (int e = 0; e < E; ++e) acc[e] = 0.f;
    for (int hh = tid; hh < H; hh += 256) {
        float xv = xf[(size_t)t * H + hh];
        const float* wr = W + (size_t)hh * E;
#pragma unroll
        for (int e = 0; e < E; ++e) acc[e] += xv * wr[e];
    }
#pragma unroll
    for (int e = 0; e < E; ++e)
#pragma unroll
        for (int off = 16; off > 0; off >>= 1)
            acc[e] += __shfl_xor_sync(0xffffffffu, acc[e], off);
    __shared__ float wsum[8][E];
    __shared__ float logit[E];
    if (lane == 0)
#pragma unroll
        for (int e = 0; e < E; ++e) wsum[warp][e] = acc[e];
    __syncthreads();
    if (tid < E) {
        float s2 = 0.f;
        for (int w = 0; w < 8; ++w) s2 += wsum[w][tid];
        logit[tid] = s2;
        if (logits_out) logits_out[(size_t)t * E + tid] = s2;
    }
    __syncthreads();
    if (tid == 0) {
        float mx = logit[0];
        for (int e = 1; e < E; ++e) mx = fmaxf(mx, logit[e]);
        float ex[E], se = 0.f;
        for (int e = 0; e < E; ++e) {
            ex[e] = __expf(logit[e] - mx);
            se += ex[e];
        }
        int i0 = 0;
        for (int e = 1; e < E; ++e)
            if (ex[e] > ex[i0]) i0 = e;
        int i1 = (i0 == 0) ? 1 : 0;
        for (int e = 0; e < E; ++e)
            if (e != i0 && ex[e] > ex[i1]) i1 = e;
        float p0 = ex[i0] / se, p1 = ex[i1] / se;
        float inv2 = 1.f / (p0 + p1);
        g_topi[2 * t] = i0;
        g_topw[2 * t] = p0 * inv2;
        g_topi[2 * t + 1] = i1;
        g_topw[2 * t + 1] = p1 * inv2;
    }
}

__global__ void plan_kernel() {
    int counts[E];
#pragma unroll
    for (int e = 0; e < E; ++e) counts[e] = 0;
    for (int a = 0; a < S * TOPK; ++a) counts[g_topi[a]]++;
    int off = 0;
    int cur[E];
    for (int e = 0; e < E; ++e) {
        g_offs[e] = off;
        cur[e] = off;
        off += counts[e];
    }
    g_offs[E] = off;
    for (int a = 0; a < S * TOPK; ++a) {
        int e = g_topi[a];
        int pos = cur[e]++;
        g_perm_token[pos] = a >> 1;
        g_tok2row[a] = pos;
    }
}

// ------------------------------ launch --------------------------------------
extern "C" void kernel_launch(void* const* d_in, const int* in_sizes, int n_in,
                              void* d_out, int out_size) {
    const float* hs = (const float*)d_in[0];
    const float* wq = (const float*)d_in[2];
    const float* wk = (const float*)d_in[3];
    const float* wv = (const float*)d_in[4];
    const float* wo = (const float*)d_in[5];
    const float* n1 = (const float*)d_in[6];
    const float* n2 = (const float*)d_in[7];
    const float* n3 = (const float*)d_in[8];
    const float* n4 = (const float*)d_in[9];
    const float* router = (const float*)d_in[10];
    const float* we_w1 = (const float*)d_in[11];
    const float* we_v = (const float*)d_in[12];
    const float* we_d = (const float*)d_in[13];
    float* out = (float*)d_out;
    float* logits_out = (out_size >= S * H + S * E) ? out + (size_t)S * H : nullptr;

    cudaFuncSetAttribute(flash_kernel,
                         cudaFuncAttributeMaxDynamicSharedMemorySize, 49408);
    cudaFuncSetAttribute(tgemm_qkv_kernel,
                         cudaFuncAttributeMaxDynamicSharedMemorySize, SMEM_BYTES);
    cudaFuncSetAttribute(tgemm_wo_kernel,
                         cudaFuncAttributeMaxDynamicSharedMemorySize, SMEM_BYTES);
    cudaFuncSetAttribute(tgemm_group_kernel,
                         cudaFuncAttributeMaxDynamicSharedMemorySize, SMEM_BYTES);

    // 1. x = rmsnorm(hs, n1) -> xn planes
    rmsnorm_kernel<<<S, 256>>>(hs, 0, n1);

    // 2. fused q/k/v projection
    tgemm_qkv_kernel<<<dim3(24, 8), 256, SMEM_BYTES>>>(wq, wk, wv);

    // 3. RoPE
    rope_kernel<<<(S * NH * 32 + 255) / 256, 256>>>(1, NH);
    rope_kernel<<<(S * NKV * 32 + 255) / 256, 256>>>(0, NKV);

    // 4. attention -> attn planes
    flash_kernel<<<dim3(S / 64, NH), 256, 49408>>>();

    // 5. output proj + residual rmsnorm -> g_hidden
    tgemm_wo_kernel<<<dim3(16, 8), 256, SMEM_BYTES>>>(wo);
    add_rmsnorm_kernel<<<S, 256>>>(hs, n2);

    // 6. MoE input norm -> xn planes + g_xnorm (router)
    rmsnorm_kernel<<<S, 256>>>(nullptr, 1, n3);

    // 7. routing + plan
    router_kernel<<<S, 256>>>(router, logits_out);
    plan_kernel<<<1, 1>>>();

    // 8. expert GEMMs; hv GEMM fuses gelu(h1)*hv -> split planes
    tgemm_group_kernel<<<dim3(F / 128, 8, E), 256, SMEM_BYTES>>>(we_w1, 0);
    tgemm_group_kernel<<<dim3(F / 128, 8, E), 256, SMEM_BYTES>>>(we_v, 1);
    tgemm_group_kernel<<<dim3(H / 128, 8, E), 256, SMEM_BYTES>>>(we_d, 2);

    // 9. combine + final residual rmsnorm
    final_kernel<<<S, 256>>>(n4, out);
}

// round 8
// speedup vs baseline: 2.9391x; 1.5000x over previous
#include <cuda_runtime.h>
#include <cuda_bf16.h>
#include <math.h>

// ---------------------------------------------------------------------------
// Decoder layer, round 8:
//  - attention-path GEMMs (QKV, WO): 3xtf32 (fp32-grade; protects routing)
//  - MoE expert GEMMs: 2-plane bf16 split (3x m16n8k16 bf16, ~1.5e-5 err)
//  - flash: fast exact tanh via __expf
// Scratch accessed ONLY as device symbols inside kernels (ATS trap).
// ---------------------------------------------------------------------------

#define S 1024
#define H 2048
#define NH 32
#define NKV 8
#define D 64
#define E 8
#define TOPK 2
#define F 4096
#define EPS 1e-5f
#define MULT 0.125f
#define CAP 30.0f

// ------------------------------ scratch (device globals) --------------------
__device__ float g_xnH[S * H];      // tf32 planes (attention path)
__device__ float g_xnL[S * H];
__device__ float g_xnorm[S * H];    // fp32 (router)
__device__ __nv_bfloat16 g_xnB0[S * H];   // bf16 planes (MoE path)
__device__ __nv_bfloat16 g_xnB1[S * H];
__device__ float g_attnH[S * H];
__device__ float g_attnL[S * H];
__device__ float g_q[S * NH * D];
__device__ float g_k[S * NKV * D];
__device__ float g_v[S * NKV * D];
__device__ float g_attnproj[S * H];
__device__ float g_hidden[S * H];
__device__ float g_h1[S * TOPK * F];
__device__ __nv_bfloat16 g_h1B0[S * TOPK * F];
__device__ __nv_bfloat16 g_h1B1[S * TOPK * F];
__device__ float g_gout[S * TOPK * H];
__device__ int   g_topi[S * TOPK];
__device__ float g_topw[S * TOPK];
__device__ int   g_offs[E + 1];
__device__ int   g_perm_token[S * TOPK];
__device__ int   g_tok2row[S * TOPK];

// ------------------------------ numeric helpers -----------------------------
__device__ __forceinline__ float f2tf32f(float x) {
    unsigned r;
    asm("cvt.rna.tf32.f32 %0, %1;" : "=r"(r) : "f"(x));
    return __uint_as_float(r);
}
__device__ __forceinline__ void tf32splitf(float x, float& hi, float& lo) {
    hi = f2tf32f(x);
    lo = f2tf32f(x - hi);
}
__device__ __forceinline__ void mma_tf32(float c[4], const unsigned a[4],
                                         const unsigned b[2]) {
    asm volatile(
        "mma.sync.aligned.m16n8k8.row.col.f32.tf32.tf32.f32 "
        "{%0,%1,%2,%3}, {%4,%5,%6,%7}, {%8,%9}, {%0,%1,%2,%3};"
        : "+f"(c[0]), "+f"(c[1]), "+f"(c[2]), "+f"(c[3])
        : "r"(a[0]), "r"(a[1]), "r"(a[2]), "r"(a[3]), "r"(b[0]), "r"(b[1]));
}
__device__ __forceinline__ void mma_bf16(float c[4], const unsigned a[4],
                                         const unsigned b[2]) {
    asm volatile(
        "mma.sync.aligned.m16n8k16.row.col.f32.bf16.bf16.f32 "
        "{%0,%1,%2,%3}, {%4,%5,%6,%7}, {%8,%9}, {%0,%1,%2,%3};"
        : "+f"(c[0]), "+f"(c[1]), "+f"(c[2]), "+f"(c[3])
        : "r"(a[0]), "r"(a[1]), "r"(a[2]), "r"(a[3]), "r"(b[0]), "r"(b[1]));
}
// pack (lo=x0, hi=x1) to bf16x2
__device__ __forceinline__ unsigned packbf(float x0, float x1) {
    unsigned d;
    asm("cvt.rn.bf16x2.f32 %0, %1, %2;" : "=r"(d) : "f"(x1), "f"(x0));
    return d;
}
// 2-plane bf16 split of an adjacent pair
__device__ __forceinline__ void bfsplit2(float x0, float x1,
                                         unsigned& p0, unsigned& p1) {
    unsigned h = packbf(x0, x1);
    float r0 = x0 - __uint_as_float(h << 16);
    float r1 = x1 - __uint_as_float(h & 0xffff0000u);
    p0 = h;
    p1 = packbf(r0, r1);
}
__device__ __forceinline__ void cpa16(unsigned dst, const void* src, bool valid) {
    int sz = valid ? 16 : 0;
    asm volatile("cp.async.ca.shared.global [%0], [%1], 16, %2;\n"
                 :: "r"(dst), "l"(src), "r"(sz));
}
__device__ __forceinline__ float tanh_fast(float x) {
    float z = __expf(-2.f * fabsf(x));
    float th = __fdividef(1.f - z, 1.f + z);
    return copysignf(th, x);
}

// ======================= tf32 GEMM (attention path) =========================
#define STG 7232
#define SMEM_TF (2 * STG * 4)

struct Ctx {
    const float *AH, *AL;
    const float *B;
    float* C;
    int N, K;
    int nBase;
    int mBase, rend;
};

__device__ __forceinline__ void stage_tf(const Ctx& g, float* sm, int sbuf,
                                         int k0, int tid) {
    unsigned base = (unsigned)__cvta_generic_to_shared(sm + sbuf * STG);
#pragma unroll
    for (int i = 0; i < 2; ++i) {
        int idx = tid + i * 256;
        int row = idx >> 2, c4 = (idx & 3) * 4;
        int grow = g.mBase + row;
        bool valid = grow < g.rend;
        size_t off = (size_t)(valid ? grow : 0) * g.K + k0 + c4;
        unsigned d = base + (unsigned)(row * 20 + c4) * 4;
        cpa16(d, g.AH + off, valid);
        cpa16(d + 2560 * 4, g.AL + off, valid);
    }
#pragma unroll
    for (int i = 0; i < 2; ++i) {
        int idx = tid + i * 256;
        int row = idx >> 5, c4 = (idx & 31) * 4;
        size_t off = (size_t)(k0 + row) * g.N + g.nBase + c4;
        unsigned d = base + (unsigned)(5120 + row * 132 + c4) * 4;
        cpa16(d, g.B + off, true);
    }
    asm volatile("cp.async.commit_group;" ::: "memory");
}

__device__ __forceinline__ void gemm_tf(const Ctx& g) {
    extern __shared__ float sm[];
    int tid = threadIdx.x;
    int lane = tid & 31, warp = tid >> 5;
    int wr = warp & 1, wc = warp >> 1;
    int mW = wr * 64, nW = wc * 32;
    int gid = lane >> 2, tig = lane & 3;

    float acc[4][4][4];
#pragma unroll
    for (int mt = 0; mt < 4; ++mt)
#pragma unroll
        for (int nt = 0; nt < 4; ++nt)
#pragma unroll
            for (int r = 0; r < 4; ++r) acc[mt][nt][r] = 0.f;

    int niters = g.K / 16;
    stage_tf(g, sm, 0, 0, tid);

    for (int it = 0; it < niters; ++it) {
        int cur = it & 1;
        if (it + 1 < niters) {
            stage_tf(g, sm, cur ^ 1, (it + 1) * 16, tid);
            asm volatile("cp.async.wait_group 1;" ::: "memory");
        } else {
            asm volatile("cp.async.wait_group 0;" ::: "memory");
        }
        __syncthreads();

        const float* AHs = sm + cur * STG;
        const float* ALs = AHs + 2560;
        const float* Bs = AHs + 5120;
#pragma unroll
        for (int kk = 0; kk < 16; kk += 8) {
            unsigned bH[4][2], bL[4][2];
#pragma unroll
            for (int nt = 0; nt < 4; ++nt) {
                int c0 = (kk + tig) * 132 + nW + nt * 8 + gid;
                int c1 = c0 + 528;
                float h0, l0, h1, l1;
                tf32splitf(Bs[c0], h0, l0);
                tf32splitf(Bs[c1], h1, l1);
                bH[nt][0] = __float_as_uint(h0);
                bL[nt][0] = __float_as_uint(l0);
                bH[nt][1] = __float_as_uint(h1);
                bL[nt][1] = __float_as_uint(l1);
            }
#pragma unroll
            for (int mt = 0; mt < 4; ++mt) {
                int r0 = (mW + mt * 16 + gid) * 20 + kk + tig;
                int r1 = r0 + 160;
                unsigned aH[4], aL[4];
                aH[0] = __float_as_uint(AHs[r0]);
                aH[1] = __float_as_uint(AHs[r1]);
                aH[2] = __float_as_uint(AHs[r0 + 4]);
                aH[3] = __float_as_uint(AHs[r1 + 4]);
                aL[0] = __float_as_uint(ALs[r0]);
                aL[1] = __float_as_uint(ALs[r1]);
                aL[2] = __float_as_uint(ALs[r0 + 4]);
                aL[3] = __float_as_uint(ALs[r1 + 4]);
#pragma unroll
                for (int nt = 0; nt < 4; ++nt) {
                    mma_tf32(acc[mt][nt], aH, bL[nt]);
                    mma_tf32(acc[mt][nt], aL, bH[nt]);
                    mma_tf32(acc[mt][nt], aH, bH[nt]);
                }
            }
        }
        __syncthreads();
    }

#pragma unroll
    for (int mt = 0; mt < 4; ++mt) {
#pragma unroll
        for (int half = 0; half < 2; ++half) {
            int r0 = g.mBase + mW + mt * 16 + gid + half * 8;
            if (r0 >= g.rend) continue;
#pragma unroll
            for (int nt = 0; nt < 4; ++nt) {
                int col = g.nBase + nW + nt * 8 + tig * 2;
                *(float2*)&g.C[(size_t)r0 * g.N + col] =
                    make_float2(acc[mt][nt][half * 2], acc[mt][nt][half * 2 + 1]);
            }
        }
    }
}

__global__ void __launch_bounds__(256, 2) tgemm_qkv_kernel(
    const float* __restrict__ wq, const float* __restrict__ wk,
    const float* __restrict__ wv) {
    int bx = blockIdx.x;
    Ctx g;
    g.AH = g_xnH; g.AL = g_xnL;
    g.K = H;
    g.mBase = blockIdx.y * 128;
    g.rend = S;
    if (bx < 16) {
        g.B = wq; g.C = g_q; g.N = 2048; g.nBase = bx * 128;
    } else if (bx < 20) {
        g.B = wk; g.C = g_k; g.N = 512; g.nBase = (bx - 16) * 128;
    } else {
        g.B = wv; g.C = g_v; g.N = 512; g.nBase = (bx - 20) * 128;
    }
    gemm_tf(g);
}

__global__ void __launch_bounds__(256, 2) tgemm_wo_kernel(
    const float* __restrict__ wo) {
    Ctx g;
    g.AH = g_attnH; g.AL = g_attnL;
    g.B = wo;
    g.C = g_attnproj;
    g.N = H; g.K = H;
    g.nBase = blockIdx.x * 128;
    g.mBase = blockIdx.y * 128;
    g.rend = S;
    gemm_tf(g);
}

// ======================= bf16x2-split GEMM (MoE path) =======================
// 128x128 block, BK=32, 8 warps, warp tile 64x32.
// smem/stage bytes: A0 128*80=10240 | A1 10240 | B 32*528=16896 -> 37376
#define BSTG 37376
#define SMEM_BF (2 * BSTG)

__global__ void __launch_bounds__(256, 2) bgemm_group_kernel(
    const float* __restrict__ W, int which) {
    int e = blockIdx.z;
    int rbeg = g_offs[e], rend = g_offs[e + 1];
    int mBase = rbeg + blockIdx.y * 128;
    if (mBase >= rend) return;

    const __nv_bfloat16 *A0, *A1;
    const float* B;
    float* C;
    int N, K, useGather, epi;
    if (which == 2) {
        A0 = g_h1B0; A1 = g_h1B1; useGather = 0; epi = 0;
        B = W + (size_t)e * F * H; C = g_gout; N = H; K = F;
    } else {
        A0 = g_xnB0; A1 = g_xnB1; useGather = 1; epi = which;
        B = W + (size_t)e * H * F; C = g_h1; N = F; K = H;
    }
    int nBase = blockIdx.x * 128;

    extern __shared__ char smc[];
    int tid = threadIdx.x;
    int lane = tid & 31, warp = tid >> 5;
    int wr = warp & 1, wc = warp >> 1;
    int mW = wr * 64, nW = wc * 32;
    int gid = lane >> 2, tig = lane & 3;

    float acc[4][4][4];
#pragma unroll
    for (int mt = 0; mt < 4; ++mt)
#pragma unroll
        for (int nt = 0; nt < 4; ++nt)
#pragma unroll
            for (int r = 0; r < 4; ++r) acc[mt][nt][r] = 0.f;

    auto stage = [&](int sbuf, int k0) {
        unsigned base = (unsigned)__cvta_generic_to_shared(smc + sbuf * BSTG);
#pragma unroll
        for (int i = 0; i < 4; ++i) {
            int idx = tid + i * 256;
            int plane = idx >> 9;
            int rem = idx & 511;
            int row = rem >> 2, ch = rem & 3;
            int grow = mBase + row;
            bool valid = grow < rend;
            int arow = valid ? (useGather ? g_perm_token[grow] : grow) : 0;
            const __nv_bfloat16* src = (plane ? A1 : A0) + (size_t)arow * K + k0 + ch * 8;
            unsigned d = base + plane * 10240 + row * 80 + ch * 16;
            cpa16(d, src, valid);
        }
#pragma unroll
        for (int i = 0; i < 4; ++i) {
            int idx = tid + i * 256;
            int row = idx >> 5, ch = idx & 31;
            const float* src = B + (size_t)(k0 + row) * N + nBase + ch * 4;
            unsigned d = base + 20480 + row * 528 + ch * 16;
            cpa16(d, src, true);
        }
        asm volatile("cp.async.commit_group;" ::: "memory");
    };

    int niters = K / 32;
    stage(0, 0);
    for (int it = 0; it < niters; ++it) {
        int cur = it & 1;
        if (it + 1 < niters) {
            stage(cur ^ 1, (it + 1) * 32);
            asm volatile("cp.async.wait_group 1;" ::: "memory");
        } else {
            asm volatile("cp.async.wait_group 0;" ::: "memory");
        }
        __syncthreads();

        const char* sb = smc + cur * BSTG;
        const float* Bs = (const float*)(sb + 20480);
#pragma unroll
        for (int s = 0; s < 2; ++s) {
            unsigned bH[4][2], bL[4][2];
#pragma unroll
            for (int nt = 0; nt < 4; ++nt) {
                int c = nW + nt * 8 + gid;
                int rb = (s * 16 + 2 * tig) * 132 + c;
                bfsplit2(Bs[rb], Bs[rb + 132], bH[nt][0], bL[nt][0]);
                bfsplit2(Bs[rb + 8 * 132], Bs[rb + 9 * 132], bH[nt][1], bL[nt][1]);
            }
#pragma unroll
            for (int mt = 0; mt < 4; ++mt) {
                int r = mW + mt * 16 + gid;
                const char* pa = sb + r * 80 + s * 32 + tig * 4;
                unsigned aH[4], aL[4];
                aH[0] = *(const unsigned*)pa;
                aH[1] = *(const unsigned*)(pa + 8 * 80);
                aH[2] = *(const unsigned*)(pa + 16);
                aH[3] = *(const unsigned*)(pa + 8 * 80 + 16);
                const char* pl = pa + 10240;
                aL[0] = *(const unsigned*)pl;
                aL[1] = *(const unsigned*)(pl + 8 * 80);
                aL[2] = *(const unsigned*)(pl + 16);
                aL[3] = *(const unsigned*)(pl + 8 * 80 + 16);
#pragma unroll
                for (int nt = 0; nt < 4; ++nt) {
                    mma_bf16(acc[mt][nt], aH, bL[nt]);
                    mma_bf16(acc[mt][nt], aL, bH[nt]);
                    mma_bf16(acc[mt][nt], aH, bH[nt]);
                }
            }
        }
        __syncthreads();
    }

#pragma unroll
    for (int mt = 0; mt < 4; ++mt) {
#pragma unroll
        for (int half = 0; half < 2; ++half) {
            int r0 = mBase + mW + mt * 16 + gid + half * 8;
            if (r0 >= rend) continue;
#pragma unroll
            for (int nt = 0; nt < 4; ++nt) {
                int col = nBase + nW + nt * 8 + tig * 2;
                float v0 = acc[mt][nt][half * 2 + 0];
                float v1 = acc[mt][nt][half * 2 + 1];
                size_t idx = (size_t)r0 * N + col;
                if (epi == 0) {
                    *(float2*)&C[idx] = make_float2(v0, v1);
                } else {
                    float a0 = g_h1[idx], a1 = g_h1[idx + 1];
                    float ge0 = 0.5f * a0 * (1.f + erff(a0 * 0.7071067811865475f));
                    float ge1 = 0.5f * a1 * (1.f + erff(a1 * 0.7071067811865475f));
                    unsigned p0, p1;
                    bfsplit2(ge0 * v0, ge1 * v1, p0, p1);
                    ((unsigned*)g_h1B0)[idx >> 1] = p0;
                    ((unsigned*)g_h1B1)[idx >> 1] = p1;
                }
            }
        }
    }
}

// ------------------------------ rmsnorm (attention input) -------------------
__global__ void rmsnorm_attn_kernel(const float* __restrict__ x,
                                    const float* __restrict__ w) {
    int row = blockIdx.x;
    int tid = threadIdx.x;
    const float* xr = x + (size_t)row * H;
    float ss = 0.f;
    float loc[8];
#pragma unroll
    for (int t = 0; t < 8; ++t) {
        float v = xr[tid + t * 256];
        loc[t] = v;
        ss += v * v;
    }
    __shared__ float red[256];
    red[tid] = ss;
    __syncthreads();
    for (int s2 = 128; s2 > 0; s2 >>= 1) {
        if (tid < s2) red[tid] += red[tid + s2];
        __syncthreads();
    }
    float inv = rsqrtf(red[0] / (float)H + EPS);
#pragma unroll
    for (int t = 0; t < 8; ++t) {
        int c = tid + t * 256;
        float y = w[c] * loc[t] * inv;
        float hi, lo;
        tf32splitf(y, hi, lo);
        g_xnH[(size_t)row * H + c] = hi;
        g_xnL[(size_t)row * H + c] = lo;
    }
}

// ------------------------------ rmsnorm (MoE input) -------------------------
// writes fp32 (router) + packed bf16 split planes
__global__ void rmsnorm_moe_kernel(const float* __restrict__ n3) {
    int row = blockIdx.x;
    int tid = threadIdx.x;
    const float* xr = g_hidden + (size_t)row * H;
    float ss = 0.f;
    float2 loc[4];
#pragma unroll
    for (int t = 0; t < 4; ++t) {
        float2 v = *(const float2*)&xr[(tid + t * 256) * 2];
        loc[t] = v;
        ss += v.x * v.x + v.y * v.y;
    }
    __shared__ float red[256];
    red[tid] = ss;
    __syncthreads();
    for (int s2 = 128; s2 > 0; s2 >>= 1) {
        if (tid < s2) red[tid] += red[tid + s2];
        __syncthreads();
    }
    float inv = rsqrtf(red[0] / (float)H + EPS);
#pragma unroll
    for (int t = 0; t < 4; ++t) {
        int c = (tid + t * 256) * 2;
        float y0 = n3[c] * loc[t].x * inv;
        float y1 = n3[c + 1] * loc[t].y * inv;
        size_t idx = (size_t)row * H + c;
        *(float2*)&g_xnorm[idx] = make_float2(y0, y1);
        unsigned p0, p1;
        bfsplit2(y0, y1, p0, p1);
        ((unsigned*)g_xnB0)[idx >> 1] = p0;
        ((unsigned*)g_xnB1)[idx >> 1] = p1;
    }
}

__global__ void add_rmsnorm_kernel(const float* __restrict__ residual,
                                   const float* __restrict__ w) {
    int row = blockIdx.x;
    int tid = threadIdx.x;
    const float* xr = g_attnproj + (size_t)row * H;
    float ss = 0.f;
    float loc[8];
#pragma unroll
    for (int t = 0; t < 8; ++t) {
        float v = xr[tid + t * 256];
        loc[t] = v;
        ss += v * v;
    }
    __shared__ float red[256];
    red[tid] = ss;
    __syncthreads();
    for (int s2 = 128; s2 > 0; s2 >>= 1) {
        if (tid < s2) red[tid] += red[tid + s2];
        __syncthreads();
    }
    float inv = rsqrtf(red[0] / (float)H + EPS);
#pragma unroll
    for (int t = 0; t < 8; ++t) {
        int c = tid + t * 256;
        g_hidden[(size_t)row * H + c] =
            residual[(size_t)row * H + c] + w[c] * loc[t] * inv;
    }
}

__global__ void final_kernel(const float* __restrict__ n4,
                             float* __restrict__ out) {
    int t = blockIdx.x;
    int tid = threadIdx.x;
    int r0 = g_tok2row[2 * t], r1 = g_tok2row[2 * t + 1];
    float w0 = g_topw[2 * t], w1 = g_topw[2 * t + 1];
    const float* a = g_gout + (size_t)r0 * H;
    const float* b = g_gout + (size_t)r1 * H;
    float ss = 0.f;
    float loc[8];
#pragma unroll
    for (int k = 0; k < 8; ++k) {
        int c = tid + k * 256;
        float v = w0 * a[c] + w1 * b[c];
        loc[k] = v;
        ss += v * v;
    }
    __shared__ float red[256];
    red[tid] = ss;
    __syncthreads();
    for (int s2 = 128; s2 > 0; s2 >>= 1) {
        if (tid < s2) red[tid] += red[tid + s2];
        __syncthreads();
    }
    float inv = rsqrtf(red[0] / (float)H + EPS);
#pragma unroll
    for (int k = 0; k < 8; ++k) {
        int c = tid + k * 256;
        out[(size_t)t * H + c] = g_hidden[(size_t)t * H + c] + n4[c] * loc[k] * inv;
    }
}

// ------------------------------ RoPE ----------------------------------------
__global__ void rope_kernel(int isQ, int nheads) {
    float* x = isQ ? g_q : g_k;
    int idx = blockIdx.x * blockDim.x + threadIdx.x;
    int total = S * nheads * 32;
    if (idx >= total) return;
    int j = idx & 31;
    int rest = idx >> 5;
    int hh = rest % nheads;
    int s = rest / nheads;
    float inv = powf(10000.f, -(2.f * (float)j) / 64.f);
    float ph = (float)s * inv;
    float sn, cs;
    sincosf(ph, &sn, &cs);
    float* p = x + ((size_t)s * nheads + hh) * 64 + j;
    float x1 = p[0], x2 = p[32];
    p[0] = x1 * cs - x2 * sn;
    p[32] = x2 * cs + x1 * sn;
}

// ------------------------------ flash attention -----------------------------
__global__ void flash_kernel() {
    const float* Q = g_q;
    const float* Kg = g_k;
    const float* Vg = g_v;
    extern __shared__ float sm[];
    float* Qs = sm;               // 64*64
    float* KT = sm + 4096;        // 64*65 (reused as P)
    float* Vs = KT + 64 * 65;     // 64*64
    int qt = blockIdx.x;
    int h = blockIdx.y;
    int kv = h >> 2;
    int tid = threadIdx.x;
    int tx = tid & 15, ty = tid >> 4;

    for (int e2 = tid; e2 < 4096; e2 += 256) {
        int r = e2 >> 6, d = e2 & 63;
        Qs[e2] = Q[(size_t)(qt * 64 + r) * H + h * 64 + d];
    }

    float m[4], l[4], acc[4][4];
#pragma unroll
    for (int i = 0; i < 4; ++i) {
        m[i] = -1e30f;
        l[i] = 0.f;
#pragma unroll
        for (int j = 0; j < 4; ++j) acc[i][j] = 0.f;
    }

    for (int kt = 0; kt <= qt; ++kt) {
        __syncthreads();
        for (int e2 = tid; e2 < 4096; e2 += 256) {
            int key = e2 >> 6, d = e2 & 63;
            KT[d * 65 + key] = Kg[(size_t)(kt * 64 + key) * (NKV * D) + kv * 64 + d];
            Vs[key * 64 + d] = Vg[(size_t)(kt * 64 + key) * (NKV * D) + kv * 64 + d];
        }
        __syncthreads();

        float s[4][4];
#pragma unroll
        for (int i = 0; i < 4; ++i)
#pragma unroll
            for (int j = 0; j < 4; ++j) s[i][j] = 0.f;
        for (int d = 0; d < 64; ++d) {
            float a[4], b[4];
#pragma unroll
            for (int i = 0; i < 4; ++i) a[i] = Qs[(ty + 16 * i) * 64 + d];
#pragma unroll
            for (int j = 0; j < 4; ++j) b[j] = KT[d * 65 + tx + 16 * j];
#pragma unroll
            for (int i = 0; i < 4; ++i)
#pragma unroll
                for (int j = 0; j < 4; ++j) s[i][j] += a[i] * b[j];
        }
#pragma unroll
        for (int i = 0; i < 4; ++i) {
            int qrow = qt * 64 + ty + 16 * i;
#pragma unroll
            for (int j = 0; j < 4; ++j) {
                int key = kt * 64 + tx + 16 * j;
                float sc = CAP * tanh_fast(s[i][j] * (MULT / CAP));
                s[i][j] = (key <= qrow) ? sc : -1e30f;
            }
        }
        __syncthreads();
#pragma unroll
        for (int i = 0; i < 4; ++i) {
            float rm = s[i][0];
#pragma unroll
            for (int j = 1; j < 4; ++j) rm = fmaxf(rm, s[i][j]);
#pragma unroll
            for (int off = 8; off > 0; off >>= 1)
                rm = fmaxf(rm, __shfl_xor_sync(0xffffffffu, rm, off));
            float mn = fmaxf(m[i], rm);
            float scale = __expf(m[i] - mn);
            float rs = 0.f;
#pragma unroll
            for (int j = 0; j < 4; ++j) {
                float pv = __expf(s[i][j] - mn);
                s[i][j] = pv;
                rs += pv;
            }
#pragma unroll
            for (int off = 8; off > 0; off >>= 1)
                rs += __shfl_xor_sync(0xffffffffu, rs, off);
            l[i] = l[i] * scale + rs;
            m[i] = mn;
#pragma unroll
            for (int j = 0; j < 4; ++j) {
                acc[i][j] *= scale;
                KT[(ty + 16 * i) * 65 + tx + 16 * j] = s[i][j];
            }
        }
        __syncthreads();
        for (int key = 0; key < 64; ++key) {
            float a[4], b[4];
#pragma unroll
            for (int i = 0; i < 4; ++i) a[i] = KT[(ty + 16 * i) * 65 + key];
#pragma unroll
            for (int j = 0; j < 4; ++j) b[j] = Vs[key * 64 + tx + 16 * j];
#pragma unroll
            for (int i = 0; i < 4; ++i)
#pragma unroll
                for (int j = 0; j < 4; ++j) acc[i][j] += a[i] * b[j];
        }
    }
#pragma unroll
    for (int i = 0; i < 4; ++i) {
        float invl = 1.f / l[i];
#pragma unroll
        for (int j = 0; j < 4; ++j) {
            float o = acc[i][j] * invl;
            float hi, lo;
            tf32splitf(o, hi, lo);
            size_t idx = (size_t)(qt * 64 + ty + 16 * i) * H + h * 64 + tx + 16 * j;
            g_attnH[idx] = hi;
            g_attnL[idx] = lo;
        }
    }
}

// ------------------------------ router --------------------------------------
__global__ void router_kernel(const float* __restrict__ W,
                              float* __restrict__ logits_out) {
    const float* xf = g_xnorm;
    int t = blockIdx.x;
    int tid = threadIdx.x;
    int lane = tid & 31, warp = tid >> 5;
    float acc[E];
#pragma unroll
    for (int e = 0; e < E; ++e) acc[e] = 0.f;
    for (int hh = tid; hh < H; hh += 256) {
        float xv = xf[(size_t)t * H + hh];
        const float* wr = W + (size_t)hh * E;
#pragma unroll
        for (int e = 0; e < E; ++e) acc[e] += xv * wr[e];
    }
#pragma unroll
    for (int e = 0; e < E; ++e)
#pragma unroll
        for (int off = 16; off > 0; off >>= 1)
            acc[e] += __shfl_xor_sync(0xffffffffu, acc[e], off);
    __shared__ float wsum[8][E];
    __shared__ float logit[E];
    if (lane == 0)
#pragma unroll
        for (int e = 0; e < E; ++e) wsum[warp][e] = acc[e];
    __syncthreads();
    if (tid < E) {
        float s2 = 0.f;
        for (int w = 0; w < 8; ++w) s2 += wsum[w][tid];
        logit[tid] = s2;
        if (logits_out) logits_out[(size_t)t * E + tid] = s2;
    }
    __syncthreads();
    if (tid == 0) {
        float mx = logit[0];
        for (int e = 1; e < E; ++e) mx = fmaxf(mx, logit[e]);
        float ex[E], se = 0.f;
        for (int e = 0; e < E; ++e) {
            ex[e] = __expf(logit[e] - mx);
            se += ex[e];
        }
        int i0 = 0;
        for (int e = 1; e < E; ++e)
            if (ex[e] > ex[i0]) i0 = e;
        int i1 = (i0 == 0) ? 1 : 0;
        for (int e = 0; e < E; ++e)
            if (e != i0 && ex[e] > ex[i1]) i1 = e;
        float p0 = ex[i0] / se, p1 = ex[i1] / se;
        float inv2 = 1.f / (p0 + p1);
        g_topi[2 * t] = i0;
        g_topw[2 * t] = p0 * inv2;
        g_topi[2 * t + 1] = i1;
        g_topw[2 * t + 1] = p1 * inv2;
    }
}

__global__ void plan_kernel() {
    int counts[E];
#pragma unroll
    for (int e = 0; e < E; ++e) counts[e] = 0;
    for (int a = 0; a < S * TOPK; ++a) counts[g_topi[a]]++;
    int off = 0;
    int cur[E];
    for (int e = 0; e < E; ++e) {
        g_offs[e] = off;
        cur[e] = off;
        off += counts[e];
    }
    g_offs[E] = off;
    for (int a = 0; a < S * TOPK; ++a) {
        int e = g_topi[a];
        int pos = cur[e]++;
        g_perm_token[pos] = a >> 1;
        g_tok2row[a] = pos;
    }
}

// ------------------------------ launch --------------------------------------
extern "C" void kernel_launch(void* const* d_in, const int* in_sizes, int n_in,
                              void* d_out, int out_size) {
    const float* hs = (const float*)d_in[0];
    const float* wq = (const float*)d_in[2];
    const float* wk = (const float*)d_in[3];
    const float* wv = (const float*)d_in[4];
    const float* wo = (const float*)d_in[5];
    const float* n1 = (const float*)d_in[6];
    const float* n2 = (const float*)d_in[7];
    const float* n3 = (const float*)d_in[8];
    const float* n4 = (const float*)d_in[9];
    const float* router = (const float*)d_in[10];
    const float* we_w1 = (const float*)d_in[11];
    const float* we_v = (const float*)d_in[12];
    const float* we_d = (const float*)d_in[13];
    float* out = (float*)d_out;
    float* logits_out = (out_size >= S * H + S * E) ? out + (size_t)S * H : nullptr;

    cudaFuncSetAttribute(flash_kernel,
                         cudaFuncAttributeMaxDynamicSharedMemorySize, 49408);
    cudaFuncSetAttribute(tgemm_qkv_kernel,
                         cudaFuncAttributeMaxDynamicSharedMemorySize, SMEM_TF);
    cudaFuncSetAttribute(tgemm_wo_kernel,
                         cudaFuncAttributeMaxDynamicSharedMemorySize, SMEM_TF);
    cudaFuncSetAttribute(bgemm_group_kernel,
                         cudaFuncAttributeMaxDynamicSharedMemorySize, SMEM_BF);

    // 1. attention input norm -> tf32 planes
    rmsnorm_attn_kernel<<<S, 256>>>(hs, n1);

    // 2. fused q/k/v projection (3xtf32)
    tgemm_qkv_kernel<<<dim3(24, 8), 256, SMEM_TF>>>(wq, wk, wv);

    // 3. RoPE
    rope_kernel<<<(S * NH * 32 + 255) / 256, 256>>>(1, NH);
    rope_kernel<<<(S * NKV * 32 + 255) / 256, 256>>>(0, NKV);

    // 4. attention -> tf32 planes
    flash_kernel<<<dim3(S / 64, NH), 256, 49408>>>();

    // 5. output proj (3xtf32) + residual rmsnorm -> g_hidden
    tgemm_wo_kernel<<<dim3(16, 8), 256, SMEM_TF>>>(wo);
    add_rmsnorm_kernel<<<S, 256>>>(hs, n2);

    // 6. MoE input norm -> fp32 (router) + bf16 split planes
    rmsnorm_moe_kernel<<<S, 256>>>(n3);

    // 7. routing + plan
    router_kernel<<<S, 256>>>(router, logits_out);
    plan_kernel<<<1, 1>>>();

    // 8. expert GEMMs (bf16x2-split tensor cores); #1 -> h1 fp32,
    //    #2 fuses gelu(h1)*acc -> bf16 planes, #3 -> gout
    bgemm_group_kernel<<<dim3(F / 128, 8, E), 256, SMEM_BF>>>(we_w1, 0);
    bgemm_group_kernel<<<dim3(F / 128, 8, E), 256, SMEM_BF>>>(we_v, 1);
    bgemm_group_kernel<<<dim3(H / 128, 8, E), 256, SMEM_BF>>>(we_d, 2);

    // 9. combine + final residual rmsnorm
    final_kernel<<<S, 256>>>(n4, out);
}